// round 9
// baseline (speedup 1.0000x reference)
#include <cuda_runtime.h>
#include <cstdint>
#include <math.h>

// ---------------------------------------------------------------------------
// Problem constants
// ---------------------------------------------------------------------------
#define T_TOK   4096
#define H_DIM   2048
#define E_NUM   32
#define I_DIM   1024
#define IS_DIM  2048
#define TOPK    8
#define NGRP    8
#define TOPKG   4

#define NT_MAX  544            // 32768/64 + 32 experts worth of pad tiles
#define ROWS_MAX (NT_MAX * 64) // 34816

// GEMM tile config
#define BM 64
#define BN 64
#define BK 32
#define LDS 36                  // padded smem row stride (floats): conflict-free
#define TSZ (64 * LDS)          // 2304 floats per 64x32 tile

// ---------------------------------------------------------------------------
// Device scratch (static globals: sanctioned scratch mechanism)
// ---------------------------------------------------------------------------
__device__ float         g_Wdense[T_TOK * E_NUM];        // dense combine weights
__device__ unsigned char g_Slot[T_TOK * E_NUM];          // slot index per (t,e)
__device__ int           g_counts[E_NUM];
__device__ int           g_off[E_NUM];
__device__ int           g_tile_e[NT_MAX];
__device__ int           g_rtok[ROWS_MAX];
__device__ float         g_rw[ROWS_MAX];
__device__ unsigned char g_rslot[ROWS_MAX];
__device__ float         g_Hb[(size_t)ROWS_MAX * I_DIM];   // routed intermediate (~142MB)
__device__ float         g_Hs[(size_t)T_TOK * IS_DIM];     // shared intermediate (32MB)
__device__ float         g_Y[(size_t)T_TOK * TOPK * H_DIM];// per-slot routed outputs (256MB)

// ---------------------------------------------------------------------------
// Small helpers
// ---------------------------------------------------------------------------
__device__ __forceinline__ unsigned f2tf(float x) {
    unsigned r;
    asm("cvt.rna.tf32.f32 %0, %1;" : "=r"(r) : "f"(x));
    return r;
}

__device__ __forceinline__ void mma_tf32(float* c, const unsigned* a, const unsigned* b) {
    asm volatile(
        "mma.sync.aligned.m16n8k8.row.col.f32.tf32.tf32.f32 "
        "{%0,%1,%2,%3}, {%4,%5,%6,%7}, {%8,%9}, {%0,%1,%2,%3};\n"
        : "+f"(c[0]), "+f"(c[1]), "+f"(c[2]), "+f"(c[3])
        : "r"(a[0]), "r"(a[1]), "r"(a[2]), "r"(a[3]), "r"(b[0]), "r"(b[1]));
}

__device__ __forceinline__ void cp16(void* sptr, const void* gptr) {
    unsigned sa = (unsigned)__cvta_generic_to_shared(sptr);
    asm volatile("cp.async.cg.shared.global [%0], [%1], 16;\n" :: "r"(sa), "l"(gptr));
}

__device__ __forceinline__ float silu_f(float x) { return x / (1.f + __expf(-x)); }

// ---------------------------------------------------------------------------
// 0) clear combine-weight matrix + counts
// ---------------------------------------------------------------------------
__global__ void k_clear() {
    int i = blockIdx.x * blockDim.x + threadIdx.x;
    if (i < T_TOK * E_NUM) g_Wdense[i] = 0.f;
    if (i < E_NUM) g_counts[i] = 0;
}

// ---------------------------------------------------------------------------
// 1) router: logits + DeepSeek-V3 group top-k routing. One warp per token.
// ---------------------------------------------------------------------------
__global__ void __launch_bounds__(128) k_router(const float* __restrict__ X,
                                                const float* __restrict__ GW,
                                                const float* __restrict__ EB) {
    const int warp = threadIdx.x >> 5;
    const int lane = threadIdx.x & 31;
    const int t = blockIdx.x * 4 + warp;

    __shared__ float ssw[4][32];
    __shared__ float ssc[4][32];

    // lane = expert: dot(hidden[t], gate_w[lane]) over H=2048, 8 accumulators
    const float* x = X + (size_t)t * H_DIM;
    const float* g = GW + (size_t)lane * H_DIM;
    float a0=0.f,a1=0.f,a2=0.f,a3=0.f,a4=0.f,a5=0.f,a6=0.f,a7=0.f;
    for (int k = 0; k < H_DIM; k += 8) {
        float4 xv0 = *(const float4*)(x + k);
        float4 gv0 = *(const float4*)(g + k);
        float4 xv1 = *(const float4*)(x + k + 4);
        float4 gv1 = *(const float4*)(g + k + 4);
        a0 += xv0.x * gv0.x;  a1 += xv0.y * gv0.y;
        a2 += xv0.z * gv0.z;  a3 += xv0.w * gv0.w;
        a4 += xv1.x * gv1.x;  a5 += xv1.y * gv1.y;
        a6 += xv1.z * gv1.z;  a7 += xv1.w * gv1.w;
    }
    float logit = ((a0 + a4) + (a1 + a5)) + ((a2 + a6) + (a3 + a7));

    // sigmoid in double for a correctly-rounded fp32 score
    double scd = 1.0 / (1.0 + exp(-(double)logit));
    float sc = (float)scd;
    float sw = sc + EB[lane];
    ssw[warp][lane] = sw;
    ssc[warp][lane] = sc;
    __syncwarp();

    if (lane == 0) {
        const float* swp = ssw[warp];
        const float* scp = ssc[warp];
        // group scores: sum of top-2 within each group of 4
        float gsc[NGRP];
#pragma unroll
        for (int gg = 0; gg < NGRP; gg++) {
            float m1 = -1e30f, m2 = -1e30f;
#pragma unroll
            for (int j = 0; j < 4; j++) {
                float v = swp[gg * 4 + j];
                if (v > m1) { m2 = m1; m1 = v; }
                else if (v > m2) m2 = v;
            }
            gsc[gg] = m1 + m2;
        }
        // top-4 groups (strict > keeps lowest index on ties, like jax)
        unsigned gmask = 0;
        for (int it = 0; it < TOPKG; it++) {
            int bg = 0; float bv = -1e30f;
            for (int gg = 0; gg < NGRP; gg++)
                if (!((gmask >> gg) & 1) && gsc[gg] > bv) { bv = gsc[gg]; bg = gg; }
            gmask |= 1u << bg;
        }
        // top-8 experts among allowed groups
        int idx[TOPK]; float wsel[TOPK]; float wsum = 0.f;
        unsigned taken = 0;
        for (int it = 0; it < TOPK; it++) {
            int be = 0; float bv = -1e30f;
            for (int ee = 0; ee < E_NUM; ee++) {
                if (!((gmask >> (ee >> 2)) & 1)) continue;
                if ((taken >> ee) & 1) continue;
                if (swp[ee] > bv) { bv = swp[ee]; be = ee; }
            }
            taken |= 1u << be;
            idx[it] = be;
            wsel[it] = scp[be];
            wsum += scp[be];
        }
        float inv = 2.5f / (wsum + 1e-20f);
        for (int it = 0; it < TOPK; it++) {
            int ee = idx[it];
            g_Wdense[(size_t)t * E_NUM + ee] = wsel[it] * inv;
            g_Slot[(size_t)t * E_NUM + ee] = (unsigned char)it;
            atomicAdd(&g_counts[ee], 1);
        }
    }
}

// ---------------------------------------------------------------------------
// 2) offsets + tile map + row-array init (single block)
// ---------------------------------------------------------------------------
__global__ void k_offsets() {
    if (threadIdx.x == 0) {
        int cum = 0;
        for (int e = 0; e < E_NUM; e++) {
            g_off[e] = cum;
            cum += (g_counts[e] + 63) & ~63;
        }
        for (int tt = 0; tt < NT_MAX; tt++) g_tile_e[tt] = -1;
        for (int e = 0; e < E_NUM; e++) {
            int t0 = g_off[e] >> 6;
            int nt = (g_counts[e] + 63) >> 6;
            for (int i = 0; i < nt; i++) g_tile_e[t0 + i] = e;
        }
    }
    for (int i = threadIdx.x; i < ROWS_MAX; i += blockDim.x) {
        g_rtok[i] = -1;
        g_rw[i] = 0.f;
        g_rslot[i] = 0;
    }
}

// ---------------------------------------------------------------------------
// 3) scatter tokens to expert row lists (deterministic block scan; 1 blk/expert)
// ---------------------------------------------------------------------------
__global__ void __launch_bounds__(1024) k_scatter() {
    const int e = blockIdx.x;
    const int tid = threadIdx.x;
    const int base_t = tid * 4;

    float w[4]; int cnt = 0;
#pragma unroll
    for (int i = 0; i < 4; i++) {
        w[i] = g_Wdense[(size_t)(base_t + i) * E_NUM + e];
        cnt += (w[i] != 0.f);
    }
    const int lane = tid & 31, wid = tid >> 5;
    int incl = cnt;
#pragma unroll
    for (int d = 1; d < 32; d <<= 1) {
        int v = __shfl_up_sync(0xFFFFFFFFu, incl, d);
        if (lane >= d) incl += v;
    }
    __shared__ int wsum[32];
    if (lane == 31) wsum[wid] = incl;
    __syncthreads();
    if (wid == 0) {
        int v = wsum[lane];
#pragma unroll
        for (int d = 1; d < 32; d <<= 1) {
            int u = __shfl_up_sync(0xFFFFFFFFu, v, d);
            if (lane >= d) v += u;
        }
        wsum[lane] = v;
    }
    __syncthreads();
    int excl = incl - cnt + (wid ? wsum[wid - 1] : 0);
    int pos = g_off[e] + excl;
#pragma unroll
    for (int i = 0; i < 4; i++) {
        if (w[i] != 0.f) {
            g_rtok[pos] = base_t + i;
            g_rw[pos] = w[i];
            g_rslot[pos] = g_Slot[(size_t)(base_t + i) * E_NUM + e];
            pos++;
        }
    }
}

// ---------------------------------------------------------------------------
// 4) up-projection GEMM: H = silu(X W1^T) * (X W3^T), tf32 mma, cp.async 2-stage
//    routed=1: A rows gathered via g_rtok, per-tile expert; routed=0: shared.
// ---------------------------------------------------------------------------
__global__ void __launch_bounds__(128) k_up(const float* __restrict__ X,
                                            const float* __restrict__ W1b,
                                            const float* __restrict__ W3b,
                                            int K, int N, int routed) {
    extern __shared__ float sm[];
    const int bx = blockIdx.x, by = blockIdx.y;
    int e = 0;
    if (routed) { e = g_tile_e[by]; if (e < 0) return; }
    const size_t wstride = (size_t)N * K;
    const float* W1 = W1b + (size_t)e * wstride;
    const float* W3 = W3b + (size_t)e * wstride;
    float* Hout = routed ? g_Hb : g_Hs;

    const int tid = threadIdx.x;
    const int lane = tid & 31;
    const int warp = tid >> 5;
    const int wm = (warp >> 1) << 5;
    const int wn = (warp & 1) << 5;

    const int lrow = tid >> 3;
    const int lcol = (tid & 7) << 2;

    const float *ap[4], *b1p[4], *b3p[4];
#pragma unroll
    for (int i = 0; i < 4; i++) {
        int r = lrow + 16 * i;
        int grow = (by << 6) + r;
        int tok = routed ? g_rtok[grow] : grow;
        if (tok < 0) tok = 0;
        ap[i] = X + (size_t)tok * K + lcol;
        int bn = (bx << 6) + r;
        b1p[i] = W1 + (size_t)bn * K + lcol;
        b3p[i] = W3 + (size_t)bn * K + lcol;
    }

    float cg[2][4][4], cu[2][4][4];
#pragma unroll
    for (int mi = 0; mi < 2; mi++)
#pragma unroll
        for (int ni = 0; ni < 4; ni++)
#pragma unroll
            for (int q = 0; q < 4; q++) { cg[mi][ni][q] = 0.f; cu[mi][ni][q] = 0.f; }

    float* st0 = sm;
    float* st1 = sm + 3 * TSZ;
    const int NT = K >> 5;

    // prefetch stage 0
    {
        float* s = st0;
#pragma unroll
        for (int i = 0; i < 4; i++) {
            int r = lrow + 16 * i;
            cp16(s + r * LDS + lcol,            ap[i]);
            cp16(s + TSZ + r * LDS + lcol,      b1p[i]);
            cp16(s + 2 * TSZ + r * LDS + lcol,  b3p[i]);
        }
        asm volatile("cp.async.commit_group;\n");
    }

    for (int kt = 0; kt < NT; kt++) {
        if (kt + 1 < NT) {
            float* s = ((kt + 1) & 1) ? st1 : st0;
            int off = (kt + 1) << 5;
#pragma unroll
            for (int i = 0; i < 4; i++) {
                int r = lrow + 16 * i;
                cp16(s + r * LDS + lcol,           ap[i] + off);
                cp16(s + TSZ + r * LDS + lcol,     b1p[i] + off);
                cp16(s + 2 * TSZ + r * LDS + lcol, b3p[i] + off);
            }
            asm volatile("cp.async.commit_group;\n");
            asm volatile("cp.async.wait_group 1;\n");
        } else {
            asm volatile("cp.async.wait_group 0;\n");
        }
        __syncthreads();
        const float* As  = (kt & 1) ? st1 : st0;
        const float* B1s = As + TSZ;
        const float* B3s = As + 2 * TSZ;
#pragma unroll
        for (int kk = 0; kk < 32; kk += 8) {
            unsigned af[2][4];
#pragma unroll
            for (int mi = 0; mi < 2; mi++) {
                const float* p = As + (wm + mi * 16 + (lane >> 2)) * LDS + kk + (lane & 3);
                af[mi][0] = f2tf(p[0]);
                af[mi][1] = f2tf(p[8 * LDS]);
                af[mi][2] = f2tf(p[4]);
                af[mi][3] = f2tf(p[8 * LDS + 4]);
            }
            unsigned b1f[4][2], b3f[4][2];
#pragma unroll
            for (int ni = 0; ni < 4; ni++) {
                const float* p = B1s + (wn + ni * 8 + (lane >> 2)) * LDS + kk + (lane & 3);
                b1f[ni][0] = f2tf(p[0]);
                b1f[ni][1] = f2tf(p[4]);
                const float* q = B3s + (wn + ni * 8 + (lane >> 2)) * LDS + kk + (lane & 3);
                b3f[ni][0] = f2tf(q[0]);
                b3f[ni][1] = f2tf(q[4]);
            }
#pragma unroll
            for (int mi = 0; mi < 2; mi++)
#pragma unroll
                for (int ni = 0; ni < 4; ni++) {
                    mma_tf32(cg[mi][ni], af[mi], b1f[ni]);
                    mma_tf32(cu[mi][ni], af[mi], b3f[ni]);
                }
        }
        __syncthreads();
    }

    const int lr = lane >> 2, lc2 = (lane & 3) << 1;
#pragma unroll
    for (int mi = 0; mi < 2; mi++)
#pragma unroll
        for (int ni = 0; ni < 4; ni++)
#pragma unroll
            for (int h = 0; h < 2; h++) {
                int row = (by << 6) + wm + mi * 16 + lr + h * 8;
                int col = (bx << 6) + wn + ni * 8 + lc2;
                float g0 = cg[mi][ni][h * 2], g1 = cg[mi][ni][h * 2 + 1];
                float u0 = cu[mi][ni][h * 2], u1 = cu[mi][ni][h * 2 + 1];
                float2 v;
                v.x = silu_f(g0) * u0;
                v.y = silu_f(g1) * u1;
                *reinterpret_cast<float2*>(&Hout[(size_t)row * N + col]) = v;
            }
}

// ---------------------------------------------------------------------------
// 5) down-projection GEMM: Y = H W2^T, scaled/scattered.
//    routed=1: reads g_Hb, writes w * y into g_Y[token][slot];
//    routed=0: reads g_Hs, writes y straight to Outp (d_out).  N fixed = 2048.
// ---------------------------------------------------------------------------
__global__ void __launch_bounds__(128) k_down(const float* __restrict__ W2b,
                                              int K, int routed,
                                              float* __restrict__ Outp) {
    __shared__ float sm[2 * 2 * TSZ];
    const int bx = blockIdx.x, by = blockIdx.y;
    const int N = H_DIM;
    int e = 0;
    if (routed) { e = g_tile_e[by]; if (e < 0) return; }
    const float* W2 = W2b + (size_t)e * N * K;
    const float* Ain = routed ? g_Hb : g_Hs;

    const int tid = threadIdx.x;
    const int lane = tid & 31;
    const int warp = tid >> 5;
    const int wm = (warp >> 1) << 5;
    const int wn = (warp & 1) << 5;
    const int lrow = tid >> 3;
    const int lcol = (tid & 7) << 2;

    const float *ap[4], *bp[4];
#pragma unroll
    for (int i = 0; i < 4; i++) {
        int r = lrow + 16 * i;
        ap[i] = Ain + (size_t)((by << 6) + r) * K + lcol;
        bp[i] = W2 + (size_t)((bx << 6) + r) * K + lcol;
    }

    float cc[2][4][4];
#pragma unroll
    for (int mi = 0; mi < 2; mi++)
#pragma unroll
        for (int ni = 0; ni < 4; ni++)
#pragma unroll
            for (int q = 0; q < 4; q++) cc[mi][ni][q] = 0.f;

    float* st0 = sm;
    float* st1 = sm + 2 * TSZ;
    const int NT = K >> 5;
    {
        float* s = st0;
#pragma unroll
        for (int i = 0; i < 4; i++) {
            int r = lrow + 16 * i;
            cp16(s + r * LDS + lcol,       ap[i]);
            cp16(s + TSZ + r * LDS + lcol, bp[i]);
        }
        asm volatile("cp.async.commit_group;\n");
    }
    for (int kt = 0; kt < NT; kt++) {
        if (kt + 1 < NT) {
            float* s = ((kt + 1) & 1) ? st1 : st0;
            int off = (kt + 1) << 5;
#pragma unroll
            for (int i = 0; i < 4; i++) {
                int r = lrow + 16 * i;
                cp16(s + r * LDS + lcol,       ap[i] + off);
                cp16(s + TSZ + r * LDS + lcol, bp[i] + off);
            }
            asm volatile("cp.async.commit_group;\n");
            asm volatile("cp.async.wait_group 1;\n");
        } else {
            asm volatile("cp.async.wait_group 0;\n");
        }
        __syncthreads();
        const float* As = (kt & 1) ? st1 : st0;
        const float* Bs = As + TSZ;
#pragma unroll
        for (int kk = 0; kk < 32; kk += 8) {
            unsigned af[2][4];
#pragma unroll
            for (int mi = 0; mi < 2; mi++) {
                const float* p = As + (wm + mi * 16 + (lane >> 2)) * LDS + kk + (lane & 3);
                af[mi][0] = f2tf(p[0]);
                af[mi][1] = f2tf(p[8 * LDS]);
                af[mi][2] = f2tf(p[4]);
                af[mi][3] = f2tf(p[8 * LDS + 4]);
            }
            unsigned bf[4][2];
#pragma unroll
            for (int ni = 0; ni < 4; ni++) {
                const float* p = Bs + (wn + ni * 8 + (lane >> 2)) * LDS + kk + (lane & 3);
                bf[ni][0] = f2tf(p[0]);
                bf[ni][1] = f2tf(p[4]);
            }
#pragma unroll
            for (int mi = 0; mi < 2; mi++)
#pragma unroll
                for (int ni = 0; ni < 4; ni++)
                    mma_tf32(cc[mi][ni], af[mi], bf[ni]);
        }
        __syncthreads();
    }

    const int lr = lane >> 2, lc2 = (lane & 3) << 1;
#pragma unroll
    for (int mi = 0; mi < 2; mi++)
#pragma unroll
        for (int ni = 0; ni < 4; ni++)
#pragma unroll
            for (int h = 0; h < 2; h++) {
                int row = (by << 6) + wm + mi * 16 + lr + h * 8;
                int col = (bx << 6) + wn + ni * 8 + lc2;
                float c0 = cc[mi][ni][h * 2], c1 = cc[mi][ni][h * 2 + 1];
                if (routed) {
                    int tok = g_rtok[row];
                    if (tok >= 0) {
                        float w = g_rw[row];
                        int slot = g_rslot[row];
                        float2 v; v.x = w * c0; v.y = w * c1;
                        *reinterpret_cast<float2*>(
                            &g_Y[((size_t)tok * TOPK + slot) * H_DIM + col]) = v;
                    }
                } else {
                    float2 v; v.x = c0; v.y = c1;
                    *reinterpret_cast<float2*>(&Outp[(size_t)row * H_DIM + col]) = v;
                }
            }
}

// ---------------------------------------------------------------------------
// 6) combine: out += sum over 8 routed slots (shared output already in out)
// ---------------------------------------------------------------------------
__global__ void k_combine(float* __restrict__ out) {
    int i = blockIdx.x * blockDim.x + threadIdx.x;  // over T*H/4 = 2,097,152
    const float4* Y4 = reinterpret_cast<const float4*>(g_Y);
    float4* O4 = reinterpret_cast<float4*>(out);
    int t = i >> 9;       // i / (2048/4)
    int c = i & 511;
    float4 acc = O4[i];
    const float4* yb = Y4 + ((size_t)t * TOPK) * 512 + c;
#pragma unroll
    for (int s = 0; s < TOPK; s++) {
        float4 v = yb[(size_t)s * 512];
        acc.x += v.x; acc.y += v.y; acc.z += v.z; acc.w += v.w;
    }
    O4[i] = acc;
}

// ---------------------------------------------------------------------------
// Launch
// ---------------------------------------------------------------------------
extern "C" void kernel_launch(void* const* d_in, const int* in_sizes, int n_in,
                              void* d_out, int out_size) {
    const float* hs  = (const float*)d_in[0];
    const float* gw  = (const float*)d_in[1];
    const float* eb  = (const float*)d_in[2];
    const float* w1  = (const float*)d_in[3];
    const float* w3  = (const float*)d_in[4];
    const float* w2  = (const float*)d_in[5];
    const float* sw1 = (const float*)d_in[6];
    const float* sw3 = (const float*)d_in[7];
    const float* sw2 = (const float*)d_in[8];
    float* out = (float*)d_out;

    cudaFuncSetAttribute((const void*)k_up,
                         cudaFuncAttributeMaxDynamicSharedMemorySize,
                         6 * TSZ * (int)sizeof(float));

    k_clear<<<512, 256>>>();
    k_router<<<T_TOK / 4, 128>>>(hs, gw, eb);
    k_offsets<<<1, 1024>>>();
    k_scatter<<<E_NUM, 1024>>>();

    // routed experts
    k_up<<<dim3(I_DIM / BN, NT_MAX), 128, 6 * TSZ * sizeof(float)>>>(
        hs, w1, w3, H_DIM, I_DIM, 1);
    k_down<<<dim3(H_DIM / BN, NT_MAX), 128>>>(w2, I_DIM, 1, nullptr);

    // shared expert (writes d_out directly)
    k_up<<<dim3(IS_DIM / BN, T_TOK / BM), 128, 6 * TSZ * sizeof(float)>>>(
        hs, sw1, sw3, H_DIM, IS_DIM, 0);
    k_down<<<dim3(H_DIM / BN, T_TOK / BM), 128>>>(sw2, IS_DIM, 0, out);

    // final combine
    k_combine<<<(T_TOK * H_DIM / 4) / 256, 256>>>(out);

    (void)in_sizes; (void)n_in; (void)out_size;
}

// round 10
// speedup vs baseline: 1.0981x; 1.0981x over previous
#include <cuda_runtime.h>
#include <cstdint>
#include <math.h>

// ---------------------------------------------------------------------------
// Problem constants
// ---------------------------------------------------------------------------
#define T_TOK   4096
#define H_DIM   2048
#define E_NUM   32
#define I_DIM   1024
#define IS_DIM  2048
#define TOPK    8
#define NGRP    8
#define TOPKG   4

#define NT_MAX   288             // 32768/128 + 32 experts of pad tiles
#define ROWS_MAX (NT_MAX * 128)  // 36864

// GEMM tile config
#define BK  32
#define LDSW 36                  // padded smem row stride (floats)

// ---------------------------------------------------------------------------
// Device scratch
// ---------------------------------------------------------------------------
__device__ float         g_Wdense[T_TOK * E_NUM];
__device__ unsigned char g_Slot[T_TOK * E_NUM];
__device__ int           g_counts[E_NUM];
__device__ int           g_off[E_NUM];
__device__ int           g_tile_e[NT_MAX];
__device__ int           g_rtok[ROWS_MAX];
__device__ float         g_rw[ROWS_MAX];
__device__ unsigned char g_rslot[ROWS_MAX];

// tf32-preconverted operands
__device__ float g_Xt[(size_t)T_TOK * H_DIM];
__device__ float g_W1t[(size_t)E_NUM * I_DIM * H_DIM];
__device__ float g_W3t[(size_t)E_NUM * I_DIM * H_DIM];
__device__ float g_W2t[(size_t)E_NUM * H_DIM * I_DIM];
__device__ float g_SW1t[(size_t)IS_DIM * H_DIM];
__device__ float g_SW3t[(size_t)IS_DIM * H_DIM];
__device__ float g_SW2t[(size_t)H_DIM * IS_DIM];

__device__ float g_Hb[(size_t)ROWS_MAX * I_DIM];     // routed intermediate (tf32 vals)
__device__ float g_Hs[(size_t)T_TOK * IS_DIM];       // shared intermediate (tf32 vals)
__device__ float g_Y[(size_t)T_TOK * TOPK * H_DIM];  // per-slot routed outputs

// ---------------------------------------------------------------------------
// Helpers
// ---------------------------------------------------------------------------
__device__ __forceinline__ unsigned f2tf(float x) {
    unsigned r;
    asm("cvt.rna.tf32.f32 %0, %1;" : "=r"(r) : "f"(x));
    return r;
}

__device__ __forceinline__ void mma_tf32(float* c, const unsigned* a, const unsigned* b) {
    asm volatile(
        "mma.sync.aligned.m16n8k8.row.col.f32.tf32.tf32.f32 "
        "{%0,%1,%2,%3}, {%4,%5,%6,%7}, {%8,%9}, {%0,%1,%2,%3};\n"
        : "+f"(c[0]), "+f"(c[1]), "+f"(c[2]), "+f"(c[3])
        : "r"(a[0]), "r"(a[1]), "r"(a[2]), "r"(a[3]), "r"(b[0]), "r"(b[1]));
}

__device__ __forceinline__ void cp16(void* sptr, const void* gptr) {
    unsigned sa = (unsigned)__cvta_generic_to_shared(sptr);
    asm volatile("cp.async.cg.shared.global [%0], [%1], 16;\n" :: "r"(sa), "l"(gptr));
}

__device__ __forceinline__ float silu_f(float x) { return x / (1.f + __expf(-x)); }

__device__ __forceinline__ unsigned lduf(const float* p) {
    return __float_as_uint(*p);   // operand already tf32-valued
}

// ---------------------------------------------------------------------------
// tf32 pre-conversion (elementwise, float4)
// ---------------------------------------------------------------------------
__global__ void k_cvt(const float4* __restrict__ in, float4* __restrict__ out, int n4) {
    int i = blockIdx.x * blockDim.x + threadIdx.x;
    if (i >= n4) return;
    float4 v = in[i];
    v.x = __uint_as_float(f2tf(v.x));
    v.y = __uint_as_float(f2tf(v.y));
    v.z = __uint_as_float(f2tf(v.z));
    v.w = __uint_as_float(f2tf(v.w));
    out[i] = v;
}

// ---------------------------------------------------------------------------
// 0) clear
// ---------------------------------------------------------------------------
__global__ void k_clear() {
    int i = blockIdx.x * blockDim.x + threadIdx.x;
    if (i < T_TOK * E_NUM) g_Wdense[i] = 0.f;
    if (i < E_NUM) g_counts[i] = 0;
}

// ---------------------------------------------------------------------------
// 1) router (one warp per token) — unchanged from passing R8 kernel
// ---------------------------------------------------------------------------
__global__ void __launch_bounds__(128) k_router(const float* __restrict__ X,
                                                const float* __restrict__ GW,
                                                const float* __restrict__ EB) {
    const int warp = threadIdx.x >> 5;
    const int lane = threadIdx.x & 31;
    const int t = blockIdx.x * 4 + warp;

    __shared__ float ssw[4][32];
    __shared__ float ssc[4][32];

    const float* x = X + (size_t)t * H_DIM;
    const float* g = GW + (size_t)lane * H_DIM;
    float a0=0.f,a1=0.f,a2=0.f,a3=0.f,a4=0.f,a5=0.f,a6=0.f,a7=0.f;
    for (int k = 0; k < H_DIM; k += 8) {
        float4 xv0 = *(const float4*)(x + k);
        float4 gv0 = *(const float4*)(g + k);
        float4 xv1 = *(const float4*)(x + k + 4);
        float4 gv1 = *(const float4*)(g + k + 4);
        a0 += xv0.x * gv0.x;  a1 += xv0.y * gv0.y;
        a2 += xv0.z * gv0.z;  a3 += xv0.w * gv0.w;
        a4 += xv1.x * gv1.x;  a5 += xv1.y * gv1.y;
        a6 += xv1.z * gv1.z;  a7 += xv1.w * gv1.w;
    }
    float logit = ((a0 + a4) + (a1 + a5)) + ((a2 + a6) + (a3 + a7));

    double scd = 1.0 / (1.0 + exp(-(double)logit));
    float sc = (float)scd;
    float sw = sc + EB[lane];
    ssw[warp][lane] = sw;
    ssc[warp][lane] = sc;
    __syncwarp();

    if (lane == 0) {
        const float* swp = ssw[warp];
        const float* scp = ssc[warp];
        float gsc[NGRP];
#pragma unroll
        for (int gg = 0; gg < NGRP; gg++) {
            float m1 = -1e30f, m2 = -1e30f;
#pragma unroll
            for (int j = 0; j < 4; j++) {
                float v = swp[gg * 4 + j];
                if (v > m1) { m2 = m1; m1 = v; }
                else if (v > m2) m2 = v;
            }
            gsc[gg] = m1 + m2;
        }
        unsigned gmask = 0;
        for (int it = 0; it < TOPKG; it++) {
            int bg = 0; float bv = -1e30f;
            for (int gg = 0; gg < NGRP; gg++)
                if (!((gmask >> gg) & 1) && gsc[gg] > bv) { bv = gsc[gg]; bg = gg; }
            gmask |= 1u << bg;
        }
        int idx[TOPK]; float wsel[TOPK]; float wsum = 0.f;
        unsigned taken = 0;
        for (int it = 0; it < TOPK; it++) {
            int be = 0; float bv = -1e30f;
            for (int ee = 0; ee < E_NUM; ee++) {
                if (!((gmask >> (ee >> 2)) & 1)) continue;
                if ((taken >> ee) & 1) continue;
                if (swp[ee] > bv) { bv = swp[ee]; be = ee; }
            }
            taken |= 1u << be;
            idx[it] = be;
            wsel[it] = scp[be];
            wsum += scp[be];
        }
        float inv = 2.5f / (wsum + 1e-20f);
        for (int it = 0; it < TOPK; it++) {
            int ee = idx[it];
            g_Wdense[(size_t)t * E_NUM + ee] = wsel[it] * inv;
            g_Slot[(size_t)t * E_NUM + ee] = (unsigned char)it;
            atomicAdd(&g_counts[ee], 1);
        }
    }
}

// ---------------------------------------------------------------------------
// 2) offsets + tile map (128-aligned) + row-array init
// ---------------------------------------------------------------------------
__global__ void k_offsets() {
    if (threadIdx.x == 0) {
        int cum = 0;
        for (int e = 0; e < E_NUM; e++) {
            g_off[e] = cum;
            cum += (g_counts[e] + 127) & ~127;
        }
        for (int tt = 0; tt < NT_MAX; tt++) g_tile_e[tt] = -1;
        for (int e = 0; e < E_NUM; e++) {
            int t0 = g_off[e] >> 7;
            int nt = (g_counts[e] + 127) >> 7;
            for (int i = 0; i < nt; i++) g_tile_e[t0 + i] = e;
        }
    }
    for (int i = threadIdx.x; i < ROWS_MAX; i += blockDim.x) {
        g_rtok[i] = -1;
        g_rw[i] = 0.f;
        g_rslot[i] = 0;
    }
}

// ---------------------------------------------------------------------------
// 3) scatter tokens to expert row lists (deterministic block scan)
// ---------------------------------------------------------------------------
__global__ void __launch_bounds__(1024) k_scatter() {
    const int e = blockIdx.x;
    const int tid = threadIdx.x;
    const int base_t = tid * 4;

    float w[4]; int cnt = 0;
#pragma unroll
    for (int i = 0; i < 4; i++) {
        w[i] = g_Wdense[(size_t)(base_t + i) * E_NUM + e];
        cnt += (w[i] != 0.f);
    }
    const int lane = tid & 31, wid = tid >> 5;
    int incl = cnt;
#pragma unroll
    for (int d = 1; d < 32; d <<= 1) {
        int v = __shfl_up_sync(0xFFFFFFFFu, incl, d);
        if (lane >= d) incl += v;
    }
    __shared__ int wsum[32];
    if (lane == 31) wsum[wid] = incl;
    __syncthreads();
    if (wid == 0) {
        int v = wsum[lane];
#pragma unroll
        for (int d = 1; d < 32; d <<= 1) {
            int u = __shfl_up_sync(0xFFFFFFFFu, v, d);
            if (lane >= d) v += u;
        }
        wsum[lane] = v;
    }
    __syncthreads();
    int excl = incl - cnt + (wid ? wsum[wid - 1] : 0);
    int pos = g_off[e] + excl;
#pragma unroll
    for (int i = 0; i < 4; i++) {
        if (w[i] != 0.f) {
            g_rtok[pos] = base_t + i;
            g_rw[pos] = w[i];
            g_rslot[pos] = g_Slot[(size_t)(base_t + i) * E_NUM + e];
            pos++;
        }
    }
}

// ---------------------------------------------------------------------------
// 4) up GEMM: H = silu(A W1^T) * (A W3^T). CTA 128x64, 256 thr, 8 warps (4x2),
//    warp tile 32x32, dual accumulators, no cvt in loop (operands tf32).
// ---------------------------------------------------------------------------
#define UP_STG (256 * LDSW)      // floats per stage: (128 A-rows + 64 B1 + 64 B3) * 36
__global__ void __launch_bounds__(256) k_up(const float* __restrict__ W1b,
                                            const float* __restrict__ W3b,
                                            int K, int N, int routed) {
    extern __shared__ float sm[];
    const int bx = blockIdx.x, by = blockIdx.y;
    int e = 0;
    if (routed) { e = g_tile_e[by]; if (e < 0) return; }
    const size_t wstride = (size_t)N * K;
    const float* W1 = W1b + (size_t)e * wstride;
    const float* W3 = W3b + (size_t)e * wstride;
    float* Hout = routed ? g_Hb : g_Hs;

    const int tid = threadIdx.x;
    const int lane = tid & 31;
    const int warp = tid >> 5;
    const int wm = (warp >> 1) << 5;   // 0,32,64,96
    const int wn = (warp & 1) << 5;    // 0,32

    // load pointers: A = 1024 cp16 chunks (4/thread), B1/B3 = 512 each (2/thread)
    const float *ap[4]; int sA[4];
#pragma unroll
    for (int i = 0; i < 4; i++) {
        int c = tid + 256 * i;
        int r = c >> 3, col = (c & 7) << 2;
        int grow = (by << 7) + r;
        int tok = routed ? g_rtok[grow] : grow;
        if (tok < 0) tok = 0;
        ap[i] = g_Xt + (size_t)tok * K + col;
        sA[i] = r * LDSW + col;
    }
    const float *b1p[2], *b3p[2]; int sB[2];
#pragma unroll
    for (int i = 0; i < 2; i++) {
        int c = tid + 256 * i;
        int r = c >> 3, col = (c & 7) << 2;
        b1p[i] = W1 + (size_t)((bx << 6) + r) * K + col;
        b3p[i] = W3 + (size_t)((bx << 6) + r) * K + col;
        sB[i] = r * LDSW + col;
    }

    float cg[2][4][4], cu[2][4][4];
#pragma unroll
    for (int mi = 0; mi < 2; mi++)
#pragma unroll
        for (int ni = 0; ni < 4; ni++)
#pragma unroll
            for (int q = 0; q < 4; q++) { cg[mi][ni][q] = 0.f; cu[mi][ni][q] = 0.f; }

    const int B1OFF = 128 * LDSW;
    const int B3OFF = 192 * LDSW;
    const int NT = K >> 5;

    {   // prefetch stage 0
        float* s = sm;
#pragma unroll
        for (int i = 0; i < 4; i++) cp16(s + sA[i], ap[i]);
#pragma unroll
        for (int i = 0; i < 2; i++) {
            cp16(s + B1OFF + sB[i], b1p[i]);
            cp16(s + B3OFF + sB[i], b3p[i]);
        }
        asm volatile("cp.async.commit_group;\n");
    }

    for (int kt = 0; kt < NT; kt++) {
        if (kt + 1 < NT) {
            float* s = sm + ((kt + 1) & 1) * UP_STG;
            int off = (kt + 1) << 5;
#pragma unroll
            for (int i = 0; i < 4; i++) cp16(s + sA[i], ap[i] + off);
#pragma unroll
            for (int i = 0; i < 2; i++) {
                cp16(s + B1OFF + sB[i], b1p[i] + off);
                cp16(s + B3OFF + sB[i], b3p[i] + off);
            }
            asm volatile("cp.async.commit_group;\n");
            asm volatile("cp.async.wait_group 1;\n");
        } else {
            asm volatile("cp.async.wait_group 0;\n");
        }
        __syncthreads();
        const float* As  = sm + (kt & 1) * UP_STG;
        const float* B1s = As + B1OFF;
        const float* B3s = As + B3OFF;
#pragma unroll
        for (int kk = 0; kk < 32; kk += 8) {
            unsigned af[2][4];
#pragma unroll
            for (int mi = 0; mi < 2; mi++) {
                const float* p = As + (wm + mi * 16 + (lane >> 2)) * LDSW + kk + (lane & 3);
                af[mi][0] = lduf(p);
                af[mi][1] = lduf(p + 8 * LDSW);
                af[mi][2] = lduf(p + 4);
                af[mi][3] = lduf(p + 8 * LDSW + 4);
            }
            unsigned b1f[4][2], b3f[4][2];
#pragma unroll
            for (int ni = 0; ni < 4; ni++) {
                const float* p = B1s + (wn + ni * 8 + (lane >> 2)) * LDSW + kk + (lane & 3);
                b1f[ni][0] = lduf(p);
                b1f[ni][1] = lduf(p + 4);
                const float* q = B3s + (wn + ni * 8 + (lane >> 2)) * LDSW + kk + (lane & 3);
                b3f[ni][0] = lduf(q);
                b3f[ni][1] = lduf(q + 4);
            }
#pragma unroll
            for (int mi = 0; mi < 2; mi++)
#pragma unroll
                for (int ni = 0; ni < 4; ni++) {
                    mma_tf32(cg[mi][ni], af[mi], b1f[ni]);
                    mma_tf32(cu[mi][ni], af[mi], b3f[ni]);
                }
        }
        __syncthreads();
    }

    const int lr = lane >> 2, lc2 = (lane & 3) << 1;
#pragma unroll
    for (int mi = 0; mi < 2; mi++)
#pragma unroll
        for (int ni = 0; ni < 4; ni++)
#pragma unroll
            for (int h = 0; h < 2; h++) {
                int row = (by << 7) + wm + mi * 16 + lr + h * 8;
                int col = (bx << 6) + wn + ni * 8 + lc2;
                float g0 = cg[mi][ni][h * 2], g1 = cg[mi][ni][h * 2 + 1];
                float u0 = cu[mi][ni][h * 2], u1 = cu[mi][ni][h * 2 + 1];
                float2 v;
                v.x = __uint_as_float(f2tf(silu_f(g0) * u0));   // store tf32-rounded
                v.y = __uint_as_float(f2tf(silu_f(g1) * u1));
                *reinterpret_cast<float2*>(&Hout[(size_t)row * N + col]) = v;
            }
}

// ---------------------------------------------------------------------------
// 5) down GEMM: Y = H W2^T. CTA 128x128, 256 thr, 8 warps (2x4), warp 64x32.
// ---------------------------------------------------------------------------
#define DN_STG (256 * LDSW)
__global__ void __launch_bounds__(256) k_down(const float* __restrict__ W2b,
                                              int K, int routed,
                                              float* __restrict__ Outp) {
    extern __shared__ float sm[];
    const int bx = blockIdx.x, by = blockIdx.y;
    const int N = H_DIM;
    int e = 0;
    if (routed) { e = g_tile_e[by]; if (e < 0) return; }
    const float* W2 = W2b + (size_t)e * N * K;
    const float* Ain = routed ? g_Hb : g_Hs;

    const int tid = threadIdx.x;
    const int lane = tid & 31;
    const int warp = tid >> 5;
    const int wm = (warp >> 2) << 6;   // 0,64
    const int wn = (warp & 3) << 5;    // 0,32,64,96

    const float *ap[4], *bp[4]; int sL[4];
#pragma unroll
    for (int i = 0; i < 4; i++) {
        int c = tid + 256 * i;
        int r = c >> 3, col = (c & 7) << 2;
        ap[i] = Ain + (size_t)((by << 7) + r) * K + col;
        bp[i] = W2 + (size_t)((bx << 7) + r) * K + col;
        sL[i] = r * LDSW + col;
    }

    float cc[4][4][4];
#pragma unroll
    for (int mi = 0; mi < 4; mi++)
#pragma unroll
        for (int ni = 0; ni < 4; ni++)
#pragma unroll
            for (int q = 0; q < 4; q++) cc[mi][ni][q] = 0.f;

    const int BOFF = 128 * LDSW;
    const int NT = K >> 5;
    {
        float* s = sm;
#pragma unroll
        for (int i = 0; i < 4; i++) {
            cp16(s + sL[i],        ap[i]);
            cp16(s + BOFF + sL[i], bp[i]);
        }
        asm volatile("cp.async.commit_group;\n");
    }
    for (int kt = 0; kt < NT; kt++) {
        if (kt + 1 < NT) {
            float* s = sm + ((kt + 1) & 1) * DN_STG;
            int off = (kt + 1) << 5;
#pragma unroll
            for (int i = 0; i < 4; i++) {
                cp16(s + sL[i],        ap[i] + off);
                cp16(s + BOFF + sL[i], bp[i] + off);
            }
            asm volatile("cp.async.commit_group;\n");
            asm volatile("cp.async.wait_group 1;\n");
        } else {
            asm volatile("cp.async.wait_group 0;\n");
        }
        __syncthreads();
        const float* As = sm + (kt & 1) * DN_STG;
        const float* Bs = As + BOFF;
#pragma unroll
        for (int kk = 0; kk < 32; kk += 8) {
            unsigned af[4][4];
#pragma unroll
            for (int mi = 0; mi < 4; mi++) {
                const float* p = As + (wm + mi * 16 + (lane >> 2)) * LDSW + kk + (lane & 3);
                af[mi][0] = lduf(p);
                af[mi][1] = lduf(p + 8 * LDSW);
                af[mi][2] = lduf(p + 4);
                af[mi][3] = lduf(p + 8 * LDSW + 4);
            }
            unsigned bf[4][2];
#pragma unroll
            for (int ni = 0; ni < 4; ni++) {
                const float* p = Bs + (wn + ni * 8 + (lane >> 2)) * LDSW + kk + (lane & 3);
                bf[ni][0] = lduf(p);
                bf[ni][1] = lduf(p + 4);
            }
#pragma unroll
            for (int mi = 0; mi < 4; mi++)
#pragma unroll
                for (int ni = 0; ni < 4; ni++)
                    mma_tf32(cc[mi][ni], af[mi], bf[ni]);
        }
        __syncthreads();
    }

    const int lr = lane >> 2, lc2 = (lane & 3) << 1;
#pragma unroll
    for (int mi = 0; mi < 4; mi++)
#pragma unroll
        for (int h = 0; h < 2; h++) {
            int row = (by << 7) + wm + mi * 16 + lr + h * 8;
            if (routed) {
                int tok = g_rtok[row];
                if (tok < 0) continue;
                float w = g_rw[row];
                int slot = g_rslot[row];
                float* yrow = &g_Y[((size_t)tok * TOPK + slot) * H_DIM];
#pragma unroll
                for (int ni = 0; ni < 4; ni++) {
                    int col = (bx << 7) + wn + ni * 8 + lc2;
                    float2 v;
                    v.x = w * cc[mi][ni][h * 2];
                    v.y = w * cc[mi][ni][h * 2 + 1];
                    *reinterpret_cast<float2*>(&yrow[col]) = v;
                }
            } else {
                float* orow = &Outp[(size_t)row * H_DIM];
#pragma unroll
                for (int ni = 0; ni < 4; ni++) {
                    int col = (bx << 7) + wn + ni * 8 + lc2;
                    float2 v;
                    v.x = cc[mi][ni][h * 2];
                    v.y = cc[mi][ni][h * 2 + 1];
                    *reinterpret_cast<float2*>(&orow[col]) = v;
                }
            }
        }
}

// ---------------------------------------------------------------------------
// 6) combine: out += sum over 8 routed slots
// ---------------------------------------------------------------------------
__global__ void k_combine(float* __restrict__ out) {
    int i = blockIdx.x * blockDim.x + threadIdx.x;
    const float4* Y4 = reinterpret_cast<const float4*>(g_Y);
    float4* O4 = reinterpret_cast<float4*>(out);
    int t = i >> 9;
    int c = i & 511;
    float4 acc = O4[i];
    const float4* yb = Y4 + ((size_t)t * TOPK) * 512 + c;
#pragma unroll
    for (int s = 0; s < TOPK; s++) {
        float4 v = yb[(size_t)s * 512];
        acc.x += v.x; acc.y += v.y; acc.z += v.z; acc.w += v.w;
    }
    O4[i] = acc;
}

// ---------------------------------------------------------------------------
// Launch
// ---------------------------------------------------------------------------
extern "C" void kernel_launch(void* const* d_in, const int* in_sizes, int n_in,
                              void* d_out, int out_size) {
    const float* hs  = (const float*)d_in[0];
    const float* gw  = (const float*)d_in[1];
    const float* eb  = (const float*)d_in[2];
    const float* w1  = (const float*)d_in[3];
    const float* w3  = (const float*)d_in[4];
    const float* w2  = (const float*)d_in[5];
    const float* sw1 = (const float*)d_in[6];
    const float* sw3 = (const float*)d_in[7];
    const float* sw2 = (const float*)d_in[8];
    float* out = (float*)d_out;

    static float* p_Xt   = nullptr;
    static float* p_W1t  = nullptr;
    static float* p_W3t  = nullptr;
    static float* p_W2t  = nullptr;
    static float* p_SW1t = nullptr;
    static float* p_SW3t = nullptr;
    static float* p_SW2t = nullptr;
    if (!p_Xt) {   // resolve device-symbol addresses once (host-side, no device work)
        cudaGetSymbolAddress((void**)&p_Xt,   g_Xt);
        cudaGetSymbolAddress((void**)&p_W1t,  g_W1t);
        cudaGetSymbolAddress((void**)&p_W3t,  g_W3t);
        cudaGetSymbolAddress((void**)&p_W2t,  g_W2t);
        cudaGetSymbolAddress((void**)&p_SW1t, g_SW1t);
        cudaGetSymbolAddress((void**)&p_SW3t, g_SW3t);
        cudaGetSymbolAddress((void**)&p_SW2t, g_SW2t);
        cudaFuncSetAttribute((const void*)k_up,
                             cudaFuncAttributeMaxDynamicSharedMemorySize,
                             2 * UP_STG * (int)sizeof(float));
        cudaFuncSetAttribute((const void*)k_down,
                             cudaFuncAttributeMaxDynamicSharedMemorySize,
                             2 * DN_STG * (int)sizeof(float));
    }

    // --- tf32 pre-conversion of all GEMM operands ---
    {
        int n4;
        n4 = T_TOK * H_DIM / 4;
        k_cvt<<<(n4 + 255) / 256, 256>>>((const float4*)hs, (float4*)p_Xt, n4);
        n4 = E_NUM * I_DIM * H_DIM / 4;
        k_cvt<<<(n4 + 255) / 256, 256>>>((const float4*)w1, (float4*)p_W1t, n4);
        k_cvt<<<(n4 + 255) / 256, 256>>>((const float4*)w3, (float4*)p_W3t, n4);
        k_cvt<<<(n4 + 255) / 256, 256>>>((const float4*)w2, (float4*)p_W2t, n4);
        n4 = IS_DIM * H_DIM / 4;
        k_cvt<<<(n4 + 255) / 256, 256>>>((const float4*)sw1, (float4*)p_SW1t, n4);
        k_cvt<<<(n4 + 255) / 256, 256>>>((const float4*)sw3, (float4*)p_SW3t, n4);
        k_cvt<<<(n4 + 255) / 256, 256>>>((const float4*)sw2, (float4*)p_SW2t, n4);
    }

    k_clear<<<512, 256>>>();
    k_router<<<T_TOK / 4, 128>>>(hs, gw, eb);
    k_offsets<<<1, 1024>>>();
    k_scatter<<<E_NUM, 1024>>>();

    // routed experts
    k_up<<<dim3(I_DIM / 64, NT_MAX), 256, 2 * UP_STG * sizeof(float)>>>(
        p_W1t, p_W3t, H_DIM, I_DIM, 1);
    k_down<<<dim3(H_DIM / 128, NT_MAX), 256, 2 * DN_STG * sizeof(float)>>>(
        p_W2t, I_DIM, 1, nullptr);

    // shared expert (writes d_out directly)
    k_up<<<dim3(IS_DIM / 64, T_TOK / 128), 256, 2 * UP_STG * sizeof(float)>>>(
        p_SW1t, p_SW3t, H_DIM, IS_DIM, 0);
    k_down<<<dim3(H_DIM / 128, T_TOK / 128), 256, 2 * DN_STG * sizeof(float)>>>(
        p_SW2t, IS_DIM, 0, out);

    // final combine
    k_combine<<<(T_TOK * H_DIM / 4) / 256, 256>>>(out);

    (void)in_sizes; (void)n_in; (void)out_size;
}

// round 11
// speedup vs baseline: 1.0985x; 1.0004x over previous
#include <cuda_runtime.h>
#include <cstdint>
#include <math.h>

// ---------------------------------------------------------------------------
// Problem constants
// ---------------------------------------------------------------------------
#define T_TOK   4096
#define H_DIM   2048
#define E_NUM   32
#define I_DIM   1024
#define IS_DIM  2048
#define TOPK    8
#define NGRP    8
#define TOPKG   4

#define NT_MAX   288             // 32768/128 + 32 experts of pad tiles
#define ROWS_MAX (NT_MAX * 128)  // 36864

// GEMM tile config
#define BK  32
#define LDSW 36                  // padded smem row stride (floats)

// ---------------------------------------------------------------------------
// Device scratch
// ---------------------------------------------------------------------------
__device__ float         g_Wdense[T_TOK * E_NUM];
__device__ unsigned char g_Slot[T_TOK * E_NUM];
__device__ int           g_counts[E_NUM];
__device__ int           g_off[E_NUM];
__device__ int           g_tile_e[NT_MAX];
__device__ int           g_rtok[ROWS_MAX];
__device__ float         g_rw[ROWS_MAX];
__device__ unsigned char g_rslot[ROWS_MAX];

// tf32-preconverted operands
__device__ float g_Xt[(size_t)T_TOK * H_DIM];
__device__ float g_W1t[(size_t)E_NUM * I_DIM * H_DIM];
__device__ float g_W3t[(size_t)E_NUM * I_DIM * H_DIM];
__device__ float g_W2t[(size_t)E_NUM * H_DIM * I_DIM];
__device__ float g_SW1t[(size_t)IS_DIM * H_DIM];
__device__ float g_SW3t[(size_t)IS_DIM * H_DIM];
__device__ float g_SW2t[(size_t)H_DIM * IS_DIM];

__device__ float g_Hb[(size_t)ROWS_MAX * I_DIM];     // routed intermediate (tf32 vals)
__device__ float g_Hs[(size_t)T_TOK * IS_DIM];       // shared intermediate (tf32 vals)
__device__ float g_Y[(size_t)T_TOK * TOPK * H_DIM];  // per-slot routed outputs

// ---------------------------------------------------------------------------
// Helpers
// ---------------------------------------------------------------------------
__device__ __forceinline__ unsigned f2tf(float x) {
    unsigned r;
    asm("cvt.rna.tf32.f32 %0, %1;" : "=r"(r) : "f"(x));
    return r;
}

__device__ __forceinline__ void mma_tf32(float* c, const unsigned* a, const unsigned* b) {
    asm volatile(
        "mma.sync.aligned.m16n8k8.row.col.f32.tf32.tf32.f32 "
        "{%0,%1,%2,%3}, {%4,%5,%6,%7}, {%8,%9}, {%0,%1,%2,%3};\n"
        : "+f"(c[0]), "+f"(c[1]), "+f"(c[2]), "+f"(c[3])
        : "r"(a[0]), "r"(a[1]), "r"(a[2]), "r"(a[3]), "r"(b[0]), "r"(b[1]));
}

__device__ __forceinline__ void cp16(void* sptr, const void* gptr) {
    unsigned sa = (unsigned)__cvta_generic_to_shared(sptr);
    asm volatile("cp.async.cg.shared.global [%0], [%1], 16;\n" :: "r"(sa), "l"(gptr));
}

__device__ __forceinline__ float silu_f(float x) { return x / (1.f + __expf(-x)); }

__device__ __forceinline__ unsigned lduf(const float* p) {
    return __float_as_uint(*p);   // operand already tf32-valued
}

// ---------------------------------------------------------------------------
// tf32 pre-conversion (elementwise, float4)
// ---------------------------------------------------------------------------
__global__ void k_cvt(const float4* __restrict__ in, float4* __restrict__ out, int n4) {
    int i = blockIdx.x * blockDim.x + threadIdx.x;
    if (i >= n4) return;
    float4 v = in[i];
    v.x = __uint_as_float(f2tf(v.x));
    v.y = __uint_as_float(f2tf(v.y));
    v.z = __uint_as_float(f2tf(v.z));
    v.w = __uint_as_float(f2tf(v.w));
    out[i] = v;
}

// ---------------------------------------------------------------------------
// 0) clear
// ---------------------------------------------------------------------------
__global__ void k_clear() {
    int i = blockIdx.x * blockDim.x + threadIdx.x;
    if (i < T_TOK * E_NUM) g_Wdense[i] = 0.f;
    if (i < E_NUM) g_counts[i] = 0;
}

// ---------------------------------------------------------------------------
// 1) router (one warp per token) — unchanged from passing R8 kernel
// ---------------------------------------------------------------------------
__global__ void __launch_bounds__(128) k_router(const float* __restrict__ X,
                                                const float* __restrict__ GW,
                                                const float* __restrict__ EB) {
    const int warp = threadIdx.x >> 5;
    const int lane = threadIdx.x & 31;
    const int t = blockIdx.x * 4 + warp;

    __shared__ float ssw[4][32];
    __shared__ float ssc[4][32];

    const float* x = X + (size_t)t * H_DIM;
    const float* g = GW + (size_t)lane * H_DIM;
    float a0=0.f,a1=0.f,a2=0.f,a3=0.f,a4=0.f,a5=0.f,a6=0.f,a7=0.f;
    for (int k = 0; k < H_DIM; k += 8) {
        float4 xv0 = *(const float4*)(x + k);
        float4 gv0 = *(const float4*)(g + k);
        float4 xv1 = *(const float4*)(x + k + 4);
        float4 gv1 = *(const float4*)(g + k + 4);
        a0 += xv0.x * gv0.x;  a1 += xv0.y * gv0.y;
        a2 += xv0.z * gv0.z;  a3 += xv0.w * gv0.w;
        a4 += xv1.x * gv1.x;  a5 += xv1.y * gv1.y;
        a6 += xv1.z * gv1.z;  a7 += xv1.w * gv1.w;
    }
    float logit = ((a0 + a4) + (a1 + a5)) + ((a2 + a6) + (a3 + a7));

    double scd = 1.0 / (1.0 + exp(-(double)logit));
    float sc = (float)scd;
    float sw = sc + EB[lane];
    ssw[warp][lane] = sw;
    ssc[warp][lane] = sc;
    __syncwarp();

    if (lane == 0) {
        const float* swp = ssw[warp];
        const float* scp = ssc[warp];
        float gsc[NGRP];
#pragma unroll
        for (int gg = 0; gg < NGRP; gg++) {
            float m1 = -1e30f, m2 = -1e30f;
#pragma unroll
            for (int j = 0; j < 4; j++) {
                float v = swp[gg * 4 + j];
                if (v > m1) { m2 = m1; m1 = v; }
                else if (v > m2) m2 = v;
            }
            gsc[gg] = m1 + m2;
        }
        unsigned gmask = 0;
        for (int it = 0; it < TOPKG; it++) {
            int bg = 0; float bv = -1e30f;
            for (int gg = 0; gg < NGRP; gg++)
                if (!((gmask >> gg) & 1) && gsc[gg] > bv) { bv = gsc[gg]; bg = gg; }
            gmask |= 1u << bg;
        }
        int idx[TOPK]; float wsel[TOPK]; float wsum = 0.f;
        unsigned taken = 0;
        for (int it = 0; it < TOPK; it++) {
            int be = 0; float bv = -1e30f;
            for (int ee = 0; ee < E_NUM; ee++) {
                if (!((gmask >> (ee >> 2)) & 1)) continue;
                if ((taken >> ee) & 1) continue;
                if (swp[ee] > bv) { bv = swp[ee]; be = ee; }
            }
            taken |= 1u << be;
            idx[it] = be;
            wsel[it] = scp[be];
            wsum += scp[be];
        }
        float inv = 2.5f / (wsum + 1e-20f);
        for (int it = 0; it < TOPK; it++) {
            int ee = idx[it];
            g_Wdense[(size_t)t * E_NUM + ee] = wsel[it] * inv;
            g_Slot[(size_t)t * E_NUM + ee] = (unsigned char)it;
            atomicAdd(&g_counts[ee], 1);
        }
    }
}

// ---------------------------------------------------------------------------
// 2) offsets + tile map (128-aligned) + row-array init
// ---------------------------------------------------------------------------
__global__ void k_offsets() {
    if (threadIdx.x == 0) {
        int cum = 0;
        for (int e = 0; e < E_NUM; e++) {
            g_off[e] = cum;
            cum += (g_counts[e] + 127) & ~127;
        }
        for (int tt = 0; tt < NT_MAX; tt++) g_tile_e[tt] = -1;
        for (int e = 0; e < E_NUM; e++) {
            int t0 = g_off[e] >> 7;
            int nt = (g_counts[e] + 127) >> 7;
            for (int i = 0; i < nt; i++) g_tile_e[t0 + i] = e;
        }
    }
    for (int i = threadIdx.x; i < ROWS_MAX; i += blockDim.x) {
        g_rtok[i] = -1;
        g_rw[i] = 0.f;
        g_rslot[i] = 0;
    }
}

// ---------------------------------------------------------------------------
// 3) scatter tokens to expert row lists (deterministic block scan)
// ---------------------------------------------------------------------------
__global__ void __launch_bounds__(1024) k_scatter() {
    const int e = blockIdx.x;
    const int tid = threadIdx.x;
    const int base_t = tid * 4;

    float w[4]; int cnt = 0;
#pragma unroll
    for (int i = 0; i < 4; i++) {
        w[i] = g_Wdense[(size_t)(base_t + i) * E_NUM + e];
        cnt += (w[i] != 0.f);
    }
    const int lane = tid & 31, wid = tid >> 5;
    int incl = cnt;
#pragma unroll
    for (int d = 1; d < 32; d <<= 1) {
        int v = __shfl_up_sync(0xFFFFFFFFu, incl, d);
        if (lane >= d) incl += v;
    }
    __shared__ int wsum[32];
    if (lane == 31) wsum[wid] = incl;
    __syncthreads();
    if (wid == 0) {
        int v = wsum[lane];
#pragma unroll
        for (int d = 1; d < 32; d <<= 1) {
            int u = __shfl_up_sync(0xFFFFFFFFu, v, d);
            if (lane >= d) v += u;
        }
        wsum[lane] = v;
    }
    __syncthreads();
    int excl = incl - cnt + (wid ? wsum[wid - 1] : 0);
    int pos = g_off[e] + excl;
#pragma unroll
    for (int i = 0; i < 4; i++) {
        if (w[i] != 0.f) {
            g_rtok[pos] = base_t + i;
            g_rw[pos] = w[i];
            g_rslot[pos] = g_Slot[(size_t)(base_t + i) * E_NUM + e];
            pos++;
        }
    }
}

// ---------------------------------------------------------------------------
// 4) up GEMM: H = silu(A W1^T) * (A W3^T). CTA 128x64, 256 thr, 8 warps (4x2),
//    warp tile 32x32, dual accumulators, no cvt in loop (operands tf32).
// ---------------------------------------------------------------------------
#define UP_STG (256 * LDSW)      // floats per stage: (128 A-rows + 64 B1 + 64 B3) * 36
__global__ void __launch_bounds__(256) k_up(const float* __restrict__ W1b,
                                            const float* __restrict__ W3b,
                                            int K, int N, int routed) {
    extern __shared__ float sm[];
    const int bx = blockIdx.x, by = blockIdx.y;
    int e = 0;
    if (routed) { e = g_tile_e[by]; if (e < 0) return; }
    const size_t wstride = (size_t)N * K;
    const float* W1 = W1b + (size_t)e * wstride;
    const float* W3 = W3b + (size_t)e * wstride;
    float* Hout = routed ? g_Hb : g_Hs;

    const int tid = threadIdx.x;
    const int lane = tid & 31;
    const int warp = tid >> 5;
    const int wm = (warp >> 1) << 5;   // 0,32,64,96
    const int wn = (warp & 1) << 5;    // 0,32

    // load pointers: A = 1024 cp16 chunks (4/thread), B1/B3 = 512 each (2/thread)
    const float *ap[4]; int sA[4];
#pragma unroll
    for (int i = 0; i < 4; i++) {
        int c = tid + 256 * i;
        int r = c >> 3, col = (c & 7) << 2;
        int grow = (by << 7) + r;
        int tok = routed ? g_rtok[grow] : grow;
        if (tok < 0) tok = 0;
        ap[i] = g_Xt + (size_t)tok * K + col;
        sA[i] = r * LDSW + col;
    }
    const float *b1p[2], *b3p[2]; int sB[2];
#pragma unroll
    for (int i = 0; i < 2; i++) {
        int c = tid + 256 * i;
        int r = c >> 3, col = (c & 7) << 2;
        b1p[i] = W1 + (size_t)((bx << 6) + r) * K + col;
        b3p[i] = W3 + (size_t)((bx << 6) + r) * K + col;
        sB[i] = r * LDSW + col;
    }

    float cg[2][4][4], cu[2][4][4];
#pragma unroll
    for (int mi = 0; mi < 2; mi++)
#pragma unroll
        for (int ni = 0; ni < 4; ni++)
#pragma unroll
            for (int q = 0; q < 4; q++) { cg[mi][ni][q] = 0.f; cu[mi][ni][q] = 0.f; }

    const int B1OFF = 128 * LDSW;
    const int B3OFF = 192 * LDSW;
    const int NT = K >> 5;

    {   // prefetch stage 0
        float* s = sm;
#pragma unroll
        for (int i = 0; i < 4; i++) cp16(s + sA[i], ap[i]);
#pragma unroll
        for (int i = 0; i < 2; i++) {
            cp16(s + B1OFF + sB[i], b1p[i]);
            cp16(s + B3OFF + sB[i], b3p[i]);
        }
        asm volatile("cp.async.commit_group;\n");
    }

    for (int kt = 0; kt < NT; kt++) {
        if (kt + 1 < NT) {
            float* s = sm + ((kt + 1) & 1) * UP_STG;
            int off = (kt + 1) << 5;
#pragma unroll
            for (int i = 0; i < 4; i++) cp16(s + sA[i], ap[i] + off);
#pragma unroll
            for (int i = 0; i < 2; i++) {
                cp16(s + B1OFF + sB[i], b1p[i] + off);
                cp16(s + B3OFF + sB[i], b3p[i] + off);
            }
            asm volatile("cp.async.commit_group;\n");
            asm volatile("cp.async.wait_group 1;\n");
        } else {
            asm volatile("cp.async.wait_group 0;\n");
        }
        __syncthreads();
        const float* As  = sm + (kt & 1) * UP_STG;
        const float* B1s = As + B1OFF;
        const float* B3s = As + B3OFF;
#pragma unroll
        for (int kk = 0; kk < 32; kk += 8) {
            unsigned af[2][4];
#pragma unroll
            for (int mi = 0; mi < 2; mi++) {
                const float* p = As + (wm + mi * 16 + (lane >> 2)) * LDSW + kk + (lane & 3);
                af[mi][0] = lduf(p);
                af[mi][1] = lduf(p + 8 * LDSW);
                af[mi][2] = lduf(p + 4);
                af[mi][3] = lduf(p + 8 * LDSW + 4);
            }
            unsigned b1f[4][2], b3f[4][2];
#pragma unroll
            for (int ni = 0; ni < 4; ni++) {
                const float* p = B1s + (wn + ni * 8 + (lane >> 2)) * LDSW + kk + (lane & 3);
                b1f[ni][0] = lduf(p);
                b1f[ni][1] = lduf(p + 4);
                const float* q = B3s + (wn + ni * 8 + (lane >> 2)) * LDSW + kk + (lane & 3);
                b3f[ni][0] = lduf(q);
                b3f[ni][1] = lduf(q + 4);
            }
#pragma unroll
            for (int mi = 0; mi < 2; mi++)
#pragma unroll
                for (int ni = 0; ni < 4; ni++) {
                    mma_tf32(cg[mi][ni], af[mi], b1f[ni]);
                    mma_tf32(cu[mi][ni], af[mi], b3f[ni]);
                }
        }
        __syncthreads();
    }

    const int lr = lane >> 2, lc2 = (lane & 3) << 1;
#pragma unroll
    for (int mi = 0; mi < 2; mi++)
#pragma unroll
        for (int ni = 0; ni < 4; ni++)
#pragma unroll
            for (int h = 0; h < 2; h++) {
                int row = (by << 7) + wm + mi * 16 + lr + h * 8;
                int col = (bx << 6) + wn + ni * 8 + lc2;
                float g0 = cg[mi][ni][h * 2], g1 = cg[mi][ni][h * 2 + 1];
                float u0 = cu[mi][ni][h * 2], u1 = cu[mi][ni][h * 2 + 1];
                float2 v;
                v.x = __uint_as_float(f2tf(silu_f(g0) * u0));   // store tf32-rounded
                v.y = __uint_as_float(f2tf(silu_f(g1) * u1));
                *reinterpret_cast<float2*>(&Hout[(size_t)row * N + col]) = v;
            }
}

// ---------------------------------------------------------------------------
// 5) down GEMM: Y = H W2^T. CTA 128x128, 256 thr, 8 warps (2x4), warp 64x32.
// ---------------------------------------------------------------------------
#define DN_STG (256 * LDSW)
__global__ void __launch_bounds__(256) k_down(const float* __restrict__ W2b,
                                              int K, int routed,
                                              float* __restrict__ Outp) {
    extern __shared__ float sm[];
    const int bx = blockIdx.x, by = blockIdx.y;
    const int N = H_DIM;
    int e = 0;
    if (routed) { e = g_tile_e[by]; if (e < 0) return; }
    const float* W2 = W2b + (size_t)e * N * K;
    const float* Ain = routed ? g_Hb : g_Hs;

    const int tid = threadIdx.x;
    const int lane = tid & 31;
    const int warp = tid >> 5;
    const int wm = (warp >> 2) << 6;   // 0,64
    const int wn = (warp & 3) << 5;    // 0,32,64,96

    const float *ap[4], *bp[4]; int sL[4];
#pragma unroll
    for (int i = 0; i < 4; i++) {
        int c = tid + 256 * i;
        int r = c >> 3, col = (c & 7) << 2;
        ap[i] = Ain + (size_t)((by << 7) + r) * K + col;
        bp[i] = W2 + (size_t)((bx << 7) + r) * K + col;
        sL[i] = r * LDSW + col;
    }

    float cc[4][4][4];
#pragma unroll
    for (int mi = 0; mi < 4; mi++)
#pragma unroll
        for (int ni = 0; ni < 4; ni++)
#pragma unroll
            for (int q = 0; q < 4; q++) cc[mi][ni][q] = 0.f;

    const int BOFF = 128 * LDSW;
    const int NT = K >> 5;
    {
        float* s = sm;
#pragma unroll
        for (int i = 0; i < 4; i++) {
            cp16(s + sL[i],        ap[i]);
            cp16(s + BOFF + sL[i], bp[i]);
        }
        asm volatile("cp.async.commit_group;\n");
    }
    for (int kt = 0; kt < NT; kt++) {
        if (kt + 1 < NT) {
            float* s = sm + ((kt + 1) & 1) * DN_STG;
            int off = (kt + 1) << 5;
#pragma unroll
            for (int i = 0; i < 4; i++) {
                cp16(s + sL[i],        ap[i] + off);
                cp16(s + BOFF + sL[i], bp[i] + off);
            }
            asm volatile("cp.async.commit_group;\n");
            asm volatile("cp.async.wait_group 1;\n");
        } else {
            asm volatile("cp.async.wait_group 0;\n");
        }
        __syncthreads();
        const float* As = sm + (kt & 1) * DN_STG;
        const float* Bs = As + BOFF;
#pragma unroll
        for (int kk = 0; kk < 32; kk += 8) {
            unsigned af[4][4];
#pragma unroll
            for (int mi = 0; mi < 4; mi++) {
                const float* p = As + (wm + mi * 16 + (lane >> 2)) * LDSW + kk + (lane & 3);
                af[mi][0] = lduf(p);
                af[mi][1] = lduf(p + 8 * LDSW);
                af[mi][2] = lduf(p + 4);
                af[mi][3] = lduf(p + 8 * LDSW + 4);
            }
            unsigned bf[4][2];
#pragma unroll
            for (int ni = 0; ni < 4; ni++) {
                const float* p = Bs + (wn + ni * 8 + (lane >> 2)) * LDSW + kk + (lane & 3);
                bf[ni][0] = lduf(p);
                bf[ni][1] = lduf(p + 4);
            }
#pragma unroll
            for (int mi = 0; mi < 4; mi++)
#pragma unroll
                for (int ni = 0; ni < 4; ni++)
                    mma_tf32(cc[mi][ni], af[mi], bf[ni]);
        }
        __syncthreads();
    }

    const int lr = lane >> 2, lc2 = (lane & 3) << 1;
#pragma unroll
    for (int mi = 0; mi < 4; mi++)
#pragma unroll
        for (int h = 0; h < 2; h++) {
            int row = (by << 7) + wm + mi * 16 + lr + h * 8;
            if (routed) {
                int tok = g_rtok[row];
                if (tok < 0) continue;
                float w = g_rw[row];
                int slot = g_rslot[row];
                float* yrow = &g_Y[((size_t)tok * TOPK + slot) * H_DIM];
#pragma unroll
                for (int ni = 0; ni < 4; ni++) {
                    int col = (bx << 7) + wn + ni * 8 + lc2;
                    float2 v;
                    v.x = w * cc[mi][ni][h * 2];
                    v.y = w * cc[mi][ni][h * 2 + 1];
                    *reinterpret_cast<float2*>(&yrow[col]) = v;
                }
            } else {
                float* orow = &Outp[(size_t)row * H_DIM];
#pragma unroll
                for (int ni = 0; ni < 4; ni++) {
                    int col = (bx << 7) + wn + ni * 8 + lc2;
                    float2 v;
                    v.x = cc[mi][ni][h * 2];
                    v.y = cc[mi][ni][h * 2 + 1];
                    *reinterpret_cast<float2*>(&orow[col]) = v;
                }
            }
        }
}

// ---------------------------------------------------------------------------
// 6) combine: out += sum over 8 routed slots
// ---------------------------------------------------------------------------
__global__ void k_combine(float* __restrict__ out) {
    int i = blockIdx.x * blockDim.x + threadIdx.x;
    const float4* Y4 = reinterpret_cast<const float4*>(g_Y);
    float4* O4 = reinterpret_cast<float4*>(out);
    int t = i >> 9;
    int c = i & 511;
    float4 acc = O4[i];
    const float4* yb = Y4 + ((size_t)t * TOPK) * 512 + c;
#pragma unroll
    for (int s = 0; s < TOPK; s++) {
        float4 v = yb[(size_t)s * 512];
        acc.x += v.x; acc.y += v.y; acc.z += v.z; acc.w += v.w;
    }
    O4[i] = acc;
}

// ---------------------------------------------------------------------------
// Launch
// ---------------------------------------------------------------------------
extern "C" void kernel_launch(void* const* d_in, const int* in_sizes, int n_in,
                              void* d_out, int out_size) {
    const float* hs  = (const float*)d_in[0];
    const float* gw  = (const float*)d_in[1];
    const float* eb  = (const float*)d_in[2];
    const float* w1  = (const float*)d_in[3];
    const float* w3  = (const float*)d_in[4];
    const float* w2  = (const float*)d_in[5];
    const float* sw1 = (const float*)d_in[6];
    const float* sw3 = (const float*)d_in[7];
    const float* sw2 = (const float*)d_in[8];
    float* out = (float*)d_out;

    static float* p_Xt   = nullptr;
    static float* p_W1t  = nullptr;
    static float* p_W3t  = nullptr;
    static float* p_W2t  = nullptr;
    static float* p_SW1t = nullptr;
    static float* p_SW3t = nullptr;
    static float* p_SW2t = nullptr;
    if (!p_Xt) {   // resolve device-symbol addresses once (host-side, no device work)
        cudaGetSymbolAddress((void**)&p_Xt,   g_Xt);
        cudaGetSymbolAddress((void**)&p_W1t,  g_W1t);
        cudaGetSymbolAddress((void**)&p_W3t,  g_W3t);
        cudaGetSymbolAddress((void**)&p_W2t,  g_W2t);
        cudaGetSymbolAddress((void**)&p_SW1t, g_SW1t);
        cudaGetSymbolAddress((void**)&p_SW3t, g_SW3t);
        cudaGetSymbolAddress((void**)&p_SW2t, g_SW2t);
        cudaFuncSetAttribute((const void*)k_up,
                             cudaFuncAttributeMaxDynamicSharedMemorySize,
                             2 * UP_STG * (int)sizeof(float));
        cudaFuncSetAttribute((const void*)k_down,
                             cudaFuncAttributeMaxDynamicSharedMemorySize,
                             2 * DN_STG * (int)sizeof(float));
    }

    // --- tf32 pre-conversion of all GEMM operands ---
    {
        int n4;
        n4 = T_TOK * H_DIM / 4;
        k_cvt<<<(n4 + 255) / 256, 256>>>((const float4*)hs, (float4*)p_Xt, n4);
        n4 = E_NUM * I_DIM * H_DIM / 4;
        k_cvt<<<(n4 + 255) / 256, 256>>>((const float4*)w1, (float4*)p_W1t, n4);
        k_cvt<<<(n4 + 255) / 256, 256>>>((const float4*)w3, (float4*)p_W3t, n4);
        k_cvt<<<(n4 + 255) / 256, 256>>>((const float4*)w2, (float4*)p_W2t, n4);
        n4 = IS_DIM * H_DIM / 4;
        k_cvt<<<(n4 + 255) / 256, 256>>>((const float4*)sw1, (float4*)p_SW1t, n4);
        k_cvt<<<(n4 + 255) / 256, 256>>>((const float4*)sw3, (float4*)p_SW3t, n4);
        k_cvt<<<(n4 + 255) / 256, 256>>>((const float4*)sw2, (float4*)p_SW2t, n4);
    }

    k_clear<<<512, 256>>>();
    k_router<<<T_TOK / 4, 128>>>(hs, gw, eb);
    k_offsets<<<1, 1024>>>();
    k_scatter<<<E_NUM, 1024>>>();

    // routed experts
    k_up<<<dim3(I_DIM / 64, NT_MAX), 256, 2 * UP_STG * sizeof(float)>>>(
        p_W1t, p_W3t, H_DIM, I_DIM, 1);
    k_down<<<dim3(H_DIM / 128, NT_MAX), 256, 2 * DN_STG * sizeof(float)>>>(
        p_W2t, I_DIM, 1, nullptr);

    // shared expert (writes d_out directly)
    k_up<<<dim3(IS_DIM / 64, T_TOK / 128), 256, 2 * UP_STG * sizeof(float)>>>(
        p_SW1t, p_SW3t, H_DIM, IS_DIM, 0);
    k_down<<<dim3(H_DIM / 128, T_TOK / 128), 256, 2 * DN_STG * sizeof(float)>>>(
        p_SW2t, IS_DIM, 0, out);

    // final combine
    k_combine<<<(T_TOK * H_DIM / 4) / 256, 256>>>(out);

    (void)in_sizes; (void)n_in; (void)out_size;
}

// round 12
// speedup vs baseline: 1.7032x; 1.5505x over previous
#include <cuda_runtime.h>
#include <cuda_fp16.h>
#include <cstdint>
#include <math.h>

// ---------------------------------------------------------------------------
// Problem constants
// ---------------------------------------------------------------------------
#define T_TOK   4096
#define H_DIM   2048
#define E_NUM   32
#define I_DIM   1024
#define IS_DIM  2048
#define TOPK    8
#define NGRP    8
#define TOPKG   4

#define NT_MAX   288             // 32768/128 + 32 experts of pad tiles
#define ROWS_MAX (NT_MAX * 128)  // 36864

// GEMM tile config (fp16 path)
#define BK     32                // K per tile (halves)
#define SROW   40                // smem row stride in halves (80B; ldmatrix conflict-free)
#define STG    (256 * SROW)      // halves per pipeline stage (A:128 rows + B:128 rows)
#define NSTAGE 3

// ---------------------------------------------------------------------------
// Device scratch
// ---------------------------------------------------------------------------
__device__ float         g_Wdense[T_TOK * E_NUM];
__device__ unsigned char g_Slot[T_TOK * E_NUM];
__device__ int           g_counts[E_NUM];
__device__ int           g_off[E_NUM];
__device__ int           g_tile_e[NT_MAX];
__device__ int           g_rtok[ROWS_MAX];
__device__ float         g_rw[ROWS_MAX];
__device__ unsigned char g_rslot[ROWS_MAX];

// fp16-preconverted operands
__device__ __half g_Xh[(size_t)T_TOK * H_DIM];
__device__ __half g_W1h[(size_t)E_NUM * I_DIM * H_DIM];
__device__ __half g_W3h[(size_t)E_NUM * I_DIM * H_DIM];
__device__ __half g_W2h[(size_t)E_NUM * H_DIM * I_DIM];
__device__ __half g_SW1h[(size_t)IS_DIM * H_DIM];
__device__ __half g_SW3h[(size_t)IS_DIM * H_DIM];
__device__ __half g_SW2h[(size_t)H_DIM * IS_DIM];

__device__ __half g_Hbh[(size_t)ROWS_MAX * I_DIM];   // routed intermediate
__device__ __half g_Hsh[(size_t)T_TOK * IS_DIM];     // shared intermediate
__device__ float  g_Y[(size_t)T_TOK * TOPK * H_DIM]; // per-slot routed outputs

// ---------------------------------------------------------------------------
// Helpers
// ---------------------------------------------------------------------------
__device__ __forceinline__ void mma_f16(float* c, const unsigned* a, const unsigned* b) {
    asm volatile(
        "mma.sync.aligned.m16n8k16.row.col.f32.f16.f16.f32 "
        "{%0,%1,%2,%3}, {%4,%5,%6,%7}, {%8,%9}, {%0,%1,%2,%3};\n"
        : "+f"(c[0]), "+f"(c[1]), "+f"(c[2]), "+f"(c[3])
        : "r"(a[0]), "r"(a[1]), "r"(a[2]), "r"(a[3]), "r"(b[0]), "r"(b[1]));
}

__device__ __forceinline__ void ldsm4(unsigned* r, const void* p) {
    unsigned a = (unsigned)__cvta_generic_to_shared(p);
    asm volatile("ldmatrix.sync.aligned.m8n8.x4.shared.b16 {%0,%1,%2,%3}, [%4];\n"
                 : "=r"(r[0]), "=r"(r[1]), "=r"(r[2]), "=r"(r[3]) : "r"(a));
}

__device__ __forceinline__ void cp16(void* sptr, const void* gptr) {
    unsigned sa = (unsigned)__cvta_generic_to_shared(sptr);
    asm volatile("cp.async.cg.shared.global [%0], [%1], 16;\n" :: "r"(sa), "l"(gptr));
}
#define CP_COMMIT() asm volatile("cp.async.commit_group;\n")
#define CP_WAIT2()  asm volatile("cp.async.wait_group 2;\n")

__device__ __forceinline__ float silu_f(float x) { return x / (1.f + __expf(-x)); }

// ---------------------------------------------------------------------------
// fp32 -> fp16 conversion, 8 elems/thread
// ---------------------------------------------------------------------------
__global__ void k_cvth(const float4* __restrict__ in, uint4* __restrict__ out, int n8) {
    int i = blockIdx.x * blockDim.x + threadIdx.x;
    if (i >= n8) return;
    float4 v0 = in[2 * i];
    float4 v1 = in[2 * i + 1];
    __half2 h[4];
    h[0] = __floats2half2_rn(v0.x, v0.y);
    h[1] = __floats2half2_rn(v0.z, v0.w);
    h[2] = __floats2half2_rn(v1.x, v1.y);
    h[3] = __floats2half2_rn(v1.z, v1.w);
    out[i] = *reinterpret_cast<uint4*>(h);
}

// ---------------------------------------------------------------------------
// 0) clear
// ---------------------------------------------------------------------------
__global__ void k_clear() {
    int i = blockIdx.x * blockDim.x + threadIdx.x;
    if (i < T_TOK * E_NUM) g_Wdense[i] = 0.f;
    if (i < E_NUM) g_counts[i] = 0;
}

// ---------------------------------------------------------------------------
// 1) router (one warp per token) — proven, unchanged
// ---------------------------------------------------------------------------
__global__ void __launch_bounds__(128) k_router(const float* __restrict__ X,
                                                const float* __restrict__ GW,
                                                const float* __restrict__ EB) {
    const int warp = threadIdx.x >> 5;
    const int lane = threadIdx.x & 31;
    const int t = blockIdx.x * 4 + warp;

    __shared__ float ssw[4][32];
    __shared__ float ssc[4][32];

    const float* x = X + (size_t)t * H_DIM;
    const float* g = GW + (size_t)lane * H_DIM;
    float a0=0.f,a1=0.f,a2=0.f,a3=0.f,a4=0.f,a5=0.f,a6=0.f,a7=0.f;
    for (int k = 0; k < H_DIM; k += 8) {
        float4 xv0 = *(const float4*)(x + k);
        float4 gv0 = *(const float4*)(g + k);
        float4 xv1 = *(const float4*)(x + k + 4);
        float4 gv1 = *(const float4*)(g + k + 4);
        a0 += xv0.x * gv0.x;  a1 += xv0.y * gv0.y;
        a2 += xv0.z * gv0.z;  a3 += xv0.w * gv0.w;
        a4 += xv1.x * gv1.x;  a5 += xv1.y * gv1.y;
        a6 += xv1.z * gv1.z;  a7 += xv1.w * gv1.w;
    }
    float logit = ((a0 + a4) + (a1 + a5)) + ((a2 + a6) + (a3 + a7));

    double scd = 1.0 / (1.0 + exp(-(double)logit));
    float sc = (float)scd;
    float sw = sc + EB[lane];
    ssw[warp][lane] = sw;
    ssc[warp][lane] = sc;
    __syncwarp();

    if (lane == 0) {
        const float* swp = ssw[warp];
        const float* scp = ssc[warp];
        float gsc[NGRP];
#pragma unroll
        for (int gg = 0; gg < NGRP; gg++) {
            float m1 = -1e30f, m2 = -1e30f;
#pragma unroll
            for (int j = 0; j < 4; j++) {
                float v = swp[gg * 4 + j];
                if (v > m1) { m2 = m1; m1 = v; }
                else if (v > m2) m2 = v;
            }
            gsc[gg] = m1 + m2;
        }
        unsigned gmask = 0;
        for (int it = 0; it < TOPKG; it++) {
            int bg = 0; float bv = -1e30f;
            for (int gg = 0; gg < NGRP; gg++)
                if (!((gmask >> gg) & 1) && gsc[gg] > bv) { bv = gsc[gg]; bg = gg; }
            gmask |= 1u << bg;
        }
        int idx[TOPK]; float wsel[TOPK]; float wsum = 0.f;
        unsigned taken = 0;
        for (int it = 0; it < TOPK; it++) {
            int be = 0; float bv = -1e30f;
            for (int ee = 0; ee < E_NUM; ee++) {
                if (!((gmask >> (ee >> 2)) & 1)) continue;
                if ((taken >> ee) & 1) continue;
                if (swp[ee] > bv) { bv = swp[ee]; be = ee; }
            }
            taken |= 1u << be;
            idx[it] = be;
            wsel[it] = scp[be];
            wsum += scp[be];
        }
        float inv = 2.5f / (wsum + 1e-20f);
        for (int it = 0; it < TOPK; it++) {
            int ee = idx[it];
            g_Wdense[(size_t)t * E_NUM + ee] = wsel[it] * inv;
            g_Slot[(size_t)t * E_NUM + ee] = (unsigned char)it;
            atomicAdd(&g_counts[ee], 1);
        }
    }
}

// ---------------------------------------------------------------------------
// 2) offsets + tile map (128-aligned) + row-array init
// ---------------------------------------------------------------------------
__global__ void k_offsets() {
    if (threadIdx.x == 0) {
        int cum = 0;
        for (int e = 0; e < E_NUM; e++) {
            g_off[e] = cum;
            cum += (g_counts[e] + 127) & ~127;
        }
        for (int tt = 0; tt < NT_MAX; tt++) g_tile_e[tt] = -1;
        for (int e = 0; e < E_NUM; e++) {
            int t0 = g_off[e] >> 7;
            int nt = (g_counts[e] + 127) >> 7;
            for (int i = 0; i < nt; i++) g_tile_e[t0 + i] = e;
        }
    }
    for (int i = threadIdx.x; i < ROWS_MAX; i += blockDim.x) {
        g_rtok[i] = -1;
        g_rw[i] = 0.f;
        g_rslot[i] = 0;
    }
}

// ---------------------------------------------------------------------------
// 3) scatter tokens to expert row lists (deterministic block scan)
// ---------------------------------------------------------------------------
__global__ void __launch_bounds__(1024) k_scatter() {
    const int e = blockIdx.x;
    const int tid = threadIdx.x;
    const int base_t = tid * 4;

    float w[4]; int cnt = 0;
#pragma unroll
    for (int i = 0; i < 4; i++) {
        w[i] = g_Wdense[(size_t)(base_t + i) * E_NUM + e];
        cnt += (w[i] != 0.f);
    }
    const int lane = tid & 31, wid = tid >> 5;
    int incl = cnt;
#pragma unroll
    for (int d = 1; d < 32; d <<= 1) {
        int v = __shfl_up_sync(0xFFFFFFFFu, incl, d);
        if (lane >= d) incl += v;
    }
    __shared__ int wsum[32];
    if (lane == 31) wsum[wid] = incl;
    __syncthreads();
    if (wid == 0) {
        int v = wsum[lane];
#pragma unroll
        for (int d = 1; d < 32; d <<= 1) {
            int u = __shfl_up_sync(0xFFFFFFFFu, v, d);
            if (lane >= d) v += u;
        }
        wsum[lane] = v;
    }
    __syncthreads();
    int excl = incl - cnt + (wid ? wsum[wid - 1] : 0);
    int pos = g_off[e] + excl;
#pragma unroll
    for (int i = 0; i < 4; i++) {
        if (w[i] != 0.f) {
            g_rtok[pos] = base_t + i;
            g_rw[pos] = w[i];
            g_rslot[pos] = g_Slot[(size_t)(base_t + i) * E_NUM + e];
            pos++;
        }
    }
}

// ---------------------------------------------------------------------------
// 4) up GEMM (fp16): H = silu(A W1^T) * (A W3^T). CTA 128x64 dual, 256 thr,
//    8 warps (4m x 2n), warp 32x32, ldmatrix + m16n8k16, 3-stage cp.async.
// ---------------------------------------------------------------------------
__global__ void __launch_bounds__(256) k_up(const __half* __restrict__ W1b,
                                            const __half* __restrict__ W3b,
                                            int K, int N, int routed) {
    extern __shared__ __half smh[];
    const int bx = blockIdx.x, by = blockIdx.y;
    int e = 0;
    if (routed) { e = g_tile_e[by]; if (e < 0) return; }
    const size_t wstride = (size_t)N * K;
    const __half* W1 = W1b + (size_t)e * wstride;
    const __half* W3 = W3b + (size_t)e * wstride;
    __half* Hout = routed ? g_Hbh : g_Hsh;

    const int tid = threadIdx.x;
    const int lane = tid & 31;
    const int warp = tid >> 5;
    const int wm = (warp >> 1) << 5;   // 0,32,64,96
    const int wn = (warp & 1) << 5;    // 0,32

    // A: 512 16B-chunks (2/thread); B1/B3: 256 chunks (1/thread each)
    const __half* apg[2]; int sAo[2];
#pragma unroll
    for (int i = 0; i < 2; i++) {
        int c = tid + 256 * i;
        int r = c >> 2, colh = (c & 3) << 3;
        int grow = (by << 7) + r;
        int tok = routed ? g_rtok[grow] : grow;
        if (tok < 0) tok = 0;
        apg[i] = g_Xh + (size_t)tok * K + colh;
        sAo[i] = r * SROW + colh;
    }
    const __half *b1g, *b3g; int sBo;
    {
        int r = tid >> 2, colh = (tid & 3) << 3;
        b1g = W1 + (size_t)((bx << 6) + r) * K + colh;
        b3g = W3 + (size_t)((bx << 6) + r) * K + colh;
        sBo = r * SROW + colh;
    }

    float cg[2][4][4], cu[2][4][4];
#pragma unroll
    for (int mi = 0; mi < 2; mi++)
#pragma unroll
        for (int ni = 0; ni < 4; ni++)
#pragma unroll
            for (int q = 0; q < 4; q++) { cg[mi][ni][q] = 0.f; cu[mi][ni][q] = 0.f; }

    const int NT = K >> 5;   // BK=32

#define UP_FETCH(KT) do {                                         \
        __half* s_ = smh + ((KT) % NSTAGE) * STG;                 \
        int off_ = (KT) << 5;                                     \
        cp16(s_ + sAo[0], apg[0] + off_);                         \
        cp16(s_ + sAo[1], apg[1] + off_);                         \
        cp16(s_ + 128 * SROW + sBo, b1g + off_);                  \
        cp16(s_ + 192 * SROW + sBo, b3g + off_);                  \
    } while (0)

    UP_FETCH(0); CP_COMMIT();
    UP_FETCH(1); CP_COMMIT();

    for (int kt = 0; kt < NT; kt++) {
        if (kt + 2 < NT) UP_FETCH(kt + 2);
        CP_COMMIT();
        CP_WAIT2();
        __syncthreads();

        const __half* As  = smh + (kt % NSTAGE) * STG;
        const __half* B1s = As + 128 * SROW;
        const __half* B3s = As + 192 * SROW;

#pragma unroll
        for (int kk = 0; kk < 2; kk++) {
            const int kb = kk << 4;
            unsigned a[2][4];
            {
                const __half* p = As + (size_t)(wm + (lane & 15)) * SROW
                                   + kb + ((lane >> 4) << 3);
                ldsm4(a[0], p);
                ldsm4(a[1], p + 16 * SROW);
            }
            unsigned b1[4][2], b3[4][2];
            {
                int row = ((lane >> 4) << 3) + (lane & 7);
                int col = kb + (((lane >> 3) & 1) << 3);
                unsigned t0[4], t1[4];
                const __half* p = B1s + (size_t)(wn + row) * SROW + col;
                ldsm4(t0, p);
                ldsm4(t1, p + 16 * SROW);
                b1[0][0]=t0[0]; b1[0][1]=t0[1]; b1[1][0]=t0[2]; b1[1][1]=t0[3];
                b1[2][0]=t1[0]; b1[2][1]=t1[1]; b1[3][0]=t1[2]; b1[3][1]=t1[3];
                const __half* q = B3s + (size_t)(wn + row) * SROW + col;
                ldsm4(t0, q);
                ldsm4(t1, q + 16 * SROW);
                b3[0][0]=t0[0]; b3[0][1]=t0[1]; b3[1][0]=t0[2]; b3[1][1]=t0[3];
                b3[2][0]=t1[0]; b3[2][1]=t1[1]; b3[3][0]=t1[2]; b3[3][1]=t1[3];
            }
#pragma unroll
            for (int mi = 0; mi < 2; mi++)
#pragma unroll
                for (int ni = 0; ni < 4; ni++) {
                    mma_f16(cg[mi][ni], a[mi], b1[ni]);
                    mma_f16(cu[mi][ni], a[mi], b3[ni]);
                }
        }
        __syncthreads();
    }
#undef UP_FETCH

    const int lr = lane >> 2, lc2 = (lane & 3) << 1;
#pragma unroll
    for (int mi = 0; mi < 2; mi++)
#pragma unroll
        for (int ni = 0; ni < 4; ni++)
#pragma unroll
            for (int h = 0; h < 2; h++) {
                int row = (by << 7) + wm + mi * 16 + lr + h * 8;
                int col = (bx << 6) + wn + ni * 8 + lc2;
                float g0 = cg[mi][ni][h * 2], g1 = cg[mi][ni][h * 2 + 1];
                float u0 = cu[mi][ni][h * 2], u1 = cu[mi][ni][h * 2 + 1];
                __half2 hv = __floats2half2_rn(silu_f(g0) * u0, silu_f(g1) * u1);
                *reinterpret_cast<__half2*>(&Hout[(size_t)row * N + col]) = hv;
            }
}

// ---------------------------------------------------------------------------
// 5) down GEMM (fp16): Y = H W2^T. CTA 128x128, 256 thr, 8 warps (2m x 4n),
//    warp 64x32, ldmatrix + m16n8k16, 3-stage cp.async.
// ---------------------------------------------------------------------------
__global__ void __launch_bounds__(256) k_down(const __half* __restrict__ W2b,
                                              int K, int routed,
                                              float* __restrict__ Outp) {
    extern __shared__ __half smh[];
    const int bx = blockIdx.x, by = blockIdx.y;
    const int N = H_DIM;
    int e = 0;
    if (routed) { e = g_tile_e[by]; if (e < 0) return; }
    const __half* W2 = W2b + (size_t)e * N * K;
    const __half* Ain = routed ? g_Hbh : g_Hsh;

    const int tid = threadIdx.x;
    const int lane = tid & 31;
    const int warp = tid >> 5;
    const int wm = (warp >> 2) << 6;   // 0,64
    const int wn = (warp & 3) << 5;    // 0,32,64,96

    const __half *apg[2], *bpg[2]; int sLo[2];
#pragma unroll
    for (int i = 0; i < 2; i++) {
        int c = tid + 256 * i;
        int r = c >> 2, colh = (c & 3) << 3;
        apg[i] = Ain + (size_t)((by << 7) + r) * K + colh;
        bpg[i] = W2 + (size_t)((bx << 7) + r) * K + colh;
        sLo[i] = r * SROW + colh;
    }

    float cc[4][4][4];
#pragma unroll
    for (int mi = 0; mi < 4; mi++)
#pragma unroll
        for (int ni = 0; ni < 4; ni++)
#pragma unroll
            for (int q = 0; q < 4; q++) cc[mi][ni][q] = 0.f;

    const int NT = K >> 5;

#define DN_FETCH(KT) do {                                         \
        __half* s_ = smh + ((KT) % NSTAGE) * STG;                 \
        int off_ = (KT) << 5;                                     \
        cp16(s_ + sLo[0], apg[0] + off_);                         \
        cp16(s_ + sLo[1], apg[1] + off_);                         \
        cp16(s_ + 128 * SROW + sLo[0], bpg[0] + off_);            \
        cp16(s_ + 128 * SROW + sLo[1], bpg[1] + off_);            \
    } while (0)

    DN_FETCH(0); CP_COMMIT();
    DN_FETCH(1); CP_COMMIT();

    for (int kt = 0; kt < NT; kt++) {
        if (kt + 2 < NT) DN_FETCH(kt + 2);
        CP_COMMIT();
        CP_WAIT2();
        __syncthreads();

        const __half* As = smh + (kt % NSTAGE) * STG;
        const __half* Bs = As + 128 * SROW;

#pragma unroll
        for (int kk = 0; kk < 2; kk++) {
            const int kb = kk << 4;
            unsigned a[4][4];
            {
                const __half* p = As + (size_t)(wm + (lane & 15)) * SROW
                                   + kb + ((lane >> 4) << 3);
#pragma unroll
                for (int mi = 0; mi < 4; mi++)
                    ldsm4(a[mi], p + mi * 16 * SROW);
            }
            unsigned b[4][2];
            {
                int row = ((lane >> 4) << 3) + (lane & 7);
                int col = kb + (((lane >> 3) & 1) << 3);
                unsigned t0[4], t1[4];
                const __half* p = Bs + (size_t)(wn + row) * SROW + col;
                ldsm4(t0, p);
                ldsm4(t1, p + 16 * SROW);
                b[0][0]=t0[0]; b[0][1]=t0[1]; b[1][0]=t0[2]; b[1][1]=t0[3];
                b[2][0]=t1[0]; b[2][1]=t1[1]; b[3][0]=t1[2]; b[3][1]=t1[3];
            }
#pragma unroll
            for (int mi = 0; mi < 4; mi++)
#pragma unroll
                for (int ni = 0; ni < 4; ni++)
                    mma_f16(cc[mi][ni], a[mi], b[ni]);
        }
        __syncthreads();
    }
#undef DN_FETCH

    const int lr = lane >> 2, lc2 = (lane & 3) << 1;
#pragma unroll
    for (int mi = 0; mi < 4; mi++)
#pragma unroll
        for (int h = 0; h < 2; h++) {
            int row = (by << 7) + wm + mi * 16 + lr + h * 8;
            if (routed) {
                int tok = g_rtok[row];
                if (tok < 0) continue;
                float w = g_rw[row];
                int slot = g_rslot[row];
                float* yrow = &g_Y[((size_t)tok * TOPK + slot) * H_DIM];
#pragma unroll
                for (int ni = 0; ni < 4; ni++) {
                    int col = (bx << 7) + wn + ni * 8 + lc2;
                    float2 v;
                    v.x = w * cc[mi][ni][h * 2];
                    v.y = w * cc[mi][ni][h * 2 + 1];
                    *reinterpret_cast<float2*>(&yrow[col]) = v;
                }
            } else {
                float* orow = &Outp[(size_t)row * H_DIM];
#pragma unroll
                for (int ni = 0; ni < 4; ni++) {
                    int col = (bx << 7) + wn + ni * 8 + lc2;
                    float2 v;
                    v.x = cc[mi][ni][h * 2];
                    v.y = cc[mi][ni][h * 2 + 1];
                    *reinterpret_cast<float2*>(&orow[col]) = v;
                }
            }
        }
}

// ---------------------------------------------------------------------------
// 6) combine: out += sum over 8 routed slots
// ---------------------------------------------------------------------------
__global__ void k_combine(float* __restrict__ out) {
    int i = blockIdx.x * blockDim.x + threadIdx.x;
    const float4* Y4 = reinterpret_cast<const float4*>(g_Y);
    float4* O4 = reinterpret_cast<float4*>(out);
    int t = i >> 9;
    int c = i & 511;
    float4 acc = O4[i];
    const float4* yb = Y4 + ((size_t)t * TOPK) * 512 + c;
#pragma unroll
    for (int s = 0; s < TOPK; s++) {
        float4 v = yb[(size_t)s * 512];
        acc.x += v.x; acc.y += v.y; acc.z += v.z; acc.w += v.w;
    }
    O4[i] = acc;
}

// ---------------------------------------------------------------------------
// Launch
// ---------------------------------------------------------------------------
extern "C" void kernel_launch(void* const* d_in, const int* in_sizes, int n_in,
                              void* d_out, int out_size) {
    const float* hs  = (const float*)d_in[0];
    const float* gw  = (const float*)d_in[1];
    const float* eb  = (const float*)d_in[2];
    const float* w1  = (const float*)d_in[3];
    const float* w3  = (const float*)d_in[4];
    const float* w2  = (const float*)d_in[5];
    const float* sw1 = (const float*)d_in[6];
    const float* sw3 = (const float*)d_in[7];
    const float* sw2 = (const float*)d_in[8];
    float* out = (float*)d_out;

    static __half* p_Xh   = nullptr;
    static __half* p_W1h  = nullptr;
    static __half* p_W3h  = nullptr;
    static __half* p_W2h  = nullptr;
    static __half* p_SW1h = nullptr;
    static __half* p_SW3h = nullptr;
    static __half* p_SW2h = nullptr;
    if (!p_Xh) {
        cudaGetSymbolAddress((void**)&p_Xh,   g_Xh);
        cudaGetSymbolAddress((void**)&p_W1h,  g_W1h);
        cudaGetSymbolAddress((void**)&p_W3h,  g_W3h);
        cudaGetSymbolAddress((void**)&p_W2h,  g_W2h);
        cudaGetSymbolAddress((void**)&p_SW1h, g_SW1h);
        cudaGetSymbolAddress((void**)&p_SW3h, g_SW3h);
        cudaGetSymbolAddress((void**)&p_SW2h, g_SW2h);
        cudaFuncSetAttribute((const void*)k_up,
                             cudaFuncAttributeMaxDynamicSharedMemorySize,
                             NSTAGE * STG * (int)sizeof(__half));
        cudaFuncSetAttribute((const void*)k_down,
                             cudaFuncAttributeMaxDynamicSharedMemorySize,
                             NSTAGE * STG * (int)sizeof(__half));
    }

    // fp32 -> fp16 pre-conversion of all GEMM operands
    {
        int n8;
        n8 = T_TOK * H_DIM / 8;
        k_cvth<<<(n8 + 255) / 256, 256>>>((const float4*)hs, (uint4*)p_Xh, n8);
        n8 = E_NUM * I_DIM * H_DIM / 8;
        k_cvth<<<(n8 + 255) / 256, 256>>>((const float4*)w1, (uint4*)p_W1h, n8);
        k_cvth<<<(n8 + 255) / 256, 256>>>((const float4*)w3, (uint4*)p_W3h, n8);
        k_cvth<<<(n8 + 255) / 256, 256>>>((const float4*)w2, (uint4*)p_W2h, n8);
        n8 = IS_DIM * H_DIM / 8;
        k_cvth<<<(n8 + 255) / 256, 256>>>((const float4*)sw1, (uint4*)p_SW1h, n8);
        k_cvth<<<(n8 + 255) / 256, 256>>>((const float4*)sw3, (uint4*)p_SW3h, n8);
        k_cvth<<<(n8 + 255) / 256, 256>>>((const float4*)sw2, (uint4*)p_SW2h, n8);
    }

    k_clear<<<512, 256>>>();
    k_router<<<T_TOK / 4, 128>>>(hs, gw, eb);
    k_offsets<<<1, 1024>>>();
    k_scatter<<<E_NUM, 1024>>>();

    const int smem = NSTAGE * STG * (int)sizeof(__half);

    // routed experts
    k_up<<<dim3(I_DIM / 64, NT_MAX), 256, smem>>>(p_W1h, p_W3h, H_DIM, I_DIM, 1);
    k_down<<<dim3(H_DIM / 128, NT_MAX), 256, smem>>>(p_W2h, I_DIM, 1, nullptr);

    // shared expert (writes d_out directly)
    k_up<<<dim3(IS_DIM / 64, T_TOK / 128), 256, smem>>>(p_SW1h, p_SW3h, H_DIM, IS_DIM, 0);
    k_down<<<dim3(H_DIM / 128, T_TOK / 128), 256, smem>>>(p_SW2h, IS_DIM, 0, out);

    // final combine
    k_combine<<<(T_TOK * H_DIM / 4) / 256, 256>>>(out);

    (void)in_sizes; (void)n_in; (void)out_size;
}

// round 14
// speedup vs baseline: 1.8065x; 1.0606x over previous
#include <cuda_runtime.h>
#include <cuda_fp16.h>
#include <cstdint>
#include <math.h>

// ---------------------------------------------------------------------------
// Problem constants
// ---------------------------------------------------------------------------
#define T_TOK   4096
#define H_DIM   2048
#define E_NUM   32
#define I_DIM   1024
#define IS_DIM  2048
#define TOPK    8
#define NGRP    8
#define TOPKG   4

#define NT_MAX   288             // 32768/128 + 32 experts of pad tiles
#define ROWS_MAX (NT_MAX * 128)  // 36864

// GEMM tile config (fp16 mma.sync path)
#define BK     32                // K per tile (halves)
#define SROW   40                // smem row stride in halves (80B; ldmatrix conflict-free)
#define STG    (256 * SROW)      // halves per pipeline stage (A:128 rows + B:128 rows)
#define NSTAGE 4

// ---------------------------------------------------------------------------
// Device scratch
// ---------------------------------------------------------------------------
__device__ float         g_Wdense[T_TOK * E_NUM];
__device__ unsigned char g_Slot[T_TOK * E_NUM];
__device__ int           g_counts[E_NUM];
__device__ int           g_off[E_NUM];
__device__ int           g_tile_e[NT_MAX];
__device__ int           g_rtok[ROWS_MAX];
__device__ float         g_rw[ROWS_MAX];
__device__ unsigned char g_rslot[ROWS_MAX];

// fp16-preconverted operands
__device__ __half g_Xh[(size_t)T_TOK * H_DIM];
__device__ __half g_W1h[(size_t)E_NUM * I_DIM * H_DIM];
__device__ __half g_W3h[(size_t)E_NUM * I_DIM * H_DIM];
__device__ __half g_W2h[(size_t)E_NUM * H_DIM * I_DIM];
__device__ __half g_SW1h[(size_t)IS_DIM * H_DIM];
__device__ __half g_SW3h[(size_t)IS_DIM * H_DIM];
__device__ __half g_SW2h[(size_t)H_DIM * IS_DIM];

__device__ __half g_Hbh[(size_t)ROWS_MAX * I_DIM];   // routed intermediate
__device__ __half g_Hsh[(size_t)T_TOK * IS_DIM];     // shared intermediate
__device__ float  g_Y[(size_t)T_TOK * TOPK * H_DIM]; // per-slot routed outputs

// ---------------------------------------------------------------------------
// Helpers
// ---------------------------------------------------------------------------
__device__ __forceinline__ void mma_f16(float* c, const unsigned* a, const unsigned* b) {
    asm volatile(
        "mma.sync.aligned.m16n8k16.row.col.f32.f16.f16.f32 "
        "{%0,%1,%2,%3}, {%4,%5,%6,%7}, {%8,%9}, {%0,%1,%2,%3};\n"
        : "+f"(c[0]), "+f"(c[1]), "+f"(c[2]), "+f"(c[3])
        : "r"(a[0]), "r"(a[1]), "r"(a[2]), "r"(a[3]), "r"(b[0]), "r"(b[1]));
}

__device__ __forceinline__ void ldsm4(unsigned* r, const void* p) {
    unsigned a = (unsigned)__cvta_generic_to_shared(p);
    asm volatile("ldmatrix.sync.aligned.m8n8.x4.shared.b16 {%0,%1,%2,%3}, [%4];\n"
                 : "=r"(r[0]), "=r"(r[1]), "=r"(r[2]), "=r"(r[3]) : "r"(a));
}

__device__ __forceinline__ void cp16(void* sptr, const void* gptr) {
    unsigned sa = (unsigned)__cvta_generic_to_shared(sptr);
    asm volatile("cp.async.cg.shared.global [%0], [%1], 16;\n" :: "r"(sa), "l"(gptr));
}
#define CP_COMMIT() asm volatile("cp.async.commit_group;\n")
#define CP_WAIT3()  asm volatile("cp.async.wait_group 3;\n")

__device__ __forceinline__ float silu_f(float x) { return x / (1.f + __expf(-x)); }

// ---------------------------------------------------------------------------
// fp32 -> fp16 conversion, 8 elems/thread
// ---------------------------------------------------------------------------
__global__ void k_cvth(const float4* __restrict__ in, uint4* __restrict__ out, int n8) {
    int i = blockIdx.x * blockDim.x + threadIdx.x;
    if (i >= n8) return;
    float4 v0 = in[2 * i];
    float4 v1 = in[2 * i + 1];
    __half2 h[4];
    h[0] = __floats2half2_rn(v0.x, v0.y);
    h[1] = __floats2half2_rn(v0.z, v0.w);
    h[2] = __floats2half2_rn(v1.x, v1.y);
    h[3] = __floats2half2_rn(v1.z, v1.w);
    out[i] = *reinterpret_cast<uint4*>(h);
}

// ---------------------------------------------------------------------------
// 0) clear
// ---------------------------------------------------------------------------
__global__ void k_clear() {
    int i = blockIdx.x * blockDim.x + threadIdx.x;
    if (i < T_TOK * E_NUM) g_Wdense[i] = 0.f;
    if (i < E_NUM) g_counts[i] = 0;
}

// ---------------------------------------------------------------------------
// 1) router (one warp per token) — proven, unchanged
// ---------------------------------------------------------------------------
__global__ void __launch_bounds__(128) k_router(const float* __restrict__ X,
                                                const float* __restrict__ GW,
                                                const float* __restrict__ EB) {
    const int warp = threadIdx.x >> 5;
    const int lane = threadIdx.x & 31;
    const int t = blockIdx.x * 4 + warp;

    __shared__ float ssw[4][32];
    __shared__ float ssc[4][32];

    const float* x = X + (size_t)t * H_DIM;
    const float* g = GW + (size_t)lane * H_DIM;
    float a0=0.f,a1=0.f,a2=0.f,a3=0.f,a4=0.f,a5=0.f,a6=0.f,a7=0.f;
    for (int k = 0; k < H_DIM; k += 8) {
        float4 xv0 = *(const float4*)(x + k);
        float4 gv0 = *(const float4*)(g + k);
        float4 xv1 = *(const float4*)(x + k + 4);
        float4 gv1 = *(const float4*)(g + k + 4);
        a0 += xv0.x * gv0.x;  a1 += xv0.y * gv0.y;
        a2 += xv0.z * gv0.z;  a3 += xv0.w * gv0.w;
        a4 += xv1.x * gv1.x;  a5 += xv1.y * gv1.y;
        a6 += xv1.z * gv1.z;  a7 += xv1.w * gv1.w;
    }
    float logit = ((a0 + a4) + (a1 + a5)) + ((a2 + a6) + (a3 + a7));

    double scd = 1.0 / (1.0 + exp(-(double)logit));
    float sc = (float)scd;
    float sw = sc + EB[lane];
    ssw[warp][lane] = sw;
    ssc[warp][lane] = sc;
    __syncwarp();

    if (lane == 0) {
        const float* swp = ssw[warp];
        const float* scp = ssc[warp];
        float gsc[NGRP];
#pragma unroll
        for (int gg = 0; gg < NGRP; gg++) {
            float m1 = -1e30f, m2 = -1e30f;
#pragma unroll
            for (int j = 0; j < 4; j++) {
                float v = swp[gg * 4 + j];
                if (v > m1) { m2 = m1; m1 = v; }
                else if (v > m2) m2 = v;
            }
            gsc[gg] = m1 + m2;
        }
        unsigned gmask = 0;
        for (int it = 0; it < TOPKG; it++) {
            int bg = 0; float bv = -1e30f;
            for (int gg = 0; gg < NGRP; gg++)
                if (!((gmask >> gg) & 1) && gsc[gg] > bv) { bv = gsc[gg]; bg = gg; }
            gmask |= 1u << bg;
        }
        int idx[TOPK]; float wsel[TOPK]; float wsum = 0.f;
        unsigned taken = 0;
        for (int it = 0; it < TOPK; it++) {
            int be = 0; float bv = -1e30f;
            for (int ee = 0; ee < E_NUM; ee++) {
                if (!((gmask >> (ee >> 2)) & 1)) continue;
                if ((taken >> ee) & 1) continue;
                if (swp[ee] > bv) { bv = swp[ee]; be = ee; }
            }
            taken |= 1u << be;
            idx[it] = be;
            wsel[it] = scp[be];
            wsum += scp[be];
        }
        float inv = 2.5f / (wsum + 1e-20f);
        for (int it = 0; it < TOPK; it++) {
            int ee = idx[it];
            g_Wdense[(size_t)t * E_NUM + ee] = wsel[it] * inv;
            g_Slot[(size_t)t * E_NUM + ee] = (unsigned char)it;
            atomicAdd(&g_counts[ee], 1);
        }
    }
}

// ---------------------------------------------------------------------------
// 2) offsets + tile map (128-aligned) + row-array init
// ---------------------------------------------------------------------------
__global__ void k_offsets() {
    if (threadIdx.x == 0) {
        int cum = 0;
        for (int e = 0; e < E_NUM; e++) {
            g_off[e] = cum;
            cum += (g_counts[e] + 127) & ~127;
        }
        for (int tt = 0; tt < NT_MAX; tt++) g_tile_e[tt] = -1;
        for (int e = 0; e < E_NUM; e++) {
            int t0 = g_off[e] >> 7;
            int nt = (g_counts[e] + 127) >> 7;
            for (int i = 0; i < nt; i++) g_tile_e[t0 + i] = e;
        }
    }
    for (int i = threadIdx.x; i < ROWS_MAX; i += blockDim.x) {
        g_rtok[i] = -1;
        g_rw[i] = 0.f;
        g_rslot[i] = 0;
    }
}

// ---------------------------------------------------------------------------
// 3) scatter tokens to expert row lists (deterministic block scan)
// ---------------------------------------------------------------------------
__global__ void __launch_bounds__(1024) k_scatter() {
    const int e = blockIdx.x;
    const int tid = threadIdx.x;
    const int base_t = tid * 4;

    float w[4]; int cnt = 0;
#pragma unroll
    for (int i = 0; i < 4; i++) {
        w[i] = g_Wdense[(size_t)(base_t + i) * E_NUM + e];
        cnt += (w[i] != 0.f);
    }
    const int lane = tid & 31, wid = tid >> 5;
    int incl = cnt;
#pragma unroll
    for (int d = 1; d < 32; d <<= 1) {
        int v = __shfl_up_sync(0xFFFFFFFFu, incl, d);
        if (lane >= d) incl += v;
    }
    __shared__ int wsum[32];
    if (lane == 31) wsum[wid] = incl;
    __syncthreads();
    if (wid == 0) {
        int v = wsum[lane];
#pragma unroll
        for (int d = 1; d < 32; d <<= 1) {
            int u = __shfl_up_sync(0xFFFFFFFFu, v, d);
            if (lane >= d) v += u;
        }
        wsum[lane] = v;
    }
    __syncthreads();
    int excl = incl - cnt + (wid ? wsum[wid - 1] : 0);
    int pos = g_off[e] + excl;
#pragma unroll
    for (int i = 0; i < 4; i++) {
        if (w[i] != 0.f) {
            g_rtok[pos] = base_t + i;
            g_rw[pos] = w[i];
            g_rslot[pos] = g_Slot[(size_t)(base_t + i) * E_NUM + e];
            pos++;
        }
    }
}

// ---------------------------------------------------------------------------
// 4) up GEMM (fp16): H = silu(A W1^T) * (A W3^T). CTA 128x64 dual, 256 thr,
//    8 warps (4m x 2n), warp 32x32, ldmatrix + m16n8k16, 4-stage cp.async,
//    2 CTAs/SM.
// ---------------------------------------------------------------------------
__global__ void __launch_bounds__(256, 2) k_up(const __half* __restrict__ W1b,
                                               const __half* __restrict__ W3b,
                                               int K, int N, int routed) {
    extern __shared__ __half smh[];
    const int bx = blockIdx.x, by = blockIdx.y;
    int e = 0;
    if (routed) { e = g_tile_e[by]; if (e < 0) return; }
    const size_t wstride = (size_t)N * K;
    const __half* W1 = W1b + (size_t)e * wstride;
    const __half* W3 = W3b + (size_t)e * wstride;
    __half* Hout = routed ? g_Hbh : g_Hsh;

    const int tid = threadIdx.x;
    const int lane = tid & 31;
    const int warp = tid >> 5;
    const int wm = (warp >> 1) << 5;   // 0,32,64,96
    const int wn = (warp & 1) << 5;    // 0,32

    // A: 512 16B-chunks (2/thread); B1/B3: 256 chunks (1/thread each)
    const __half* apg[2]; int sAo[2];
#pragma unroll
    for (int i = 0; i < 2; i++) {
        int c = tid + 256 * i;
        int r = c >> 2, colh = (c & 3) << 3;
        int grow = (by << 7) + r;
        int tok = routed ? g_rtok[grow] : grow;
        if (tok < 0) tok = 0;
        apg[i] = g_Xh + (size_t)tok * K + colh;
        sAo[i] = r * SROW + colh;
    }
    const __half *b1g, *b3g; int sBo;
    {
        int r = tid >> 2, colh = (tid & 3) << 3;
        b1g = W1 + (size_t)((bx << 6) + r) * K + colh;
        b3g = W3 + (size_t)((bx << 6) + r) * K + colh;
        sBo = r * SROW + colh;
    }

    float cg[2][4][4], cu[2][4][4];
#pragma unroll
    for (int mi = 0; mi < 2; mi++)
#pragma unroll
        for (int ni = 0; ni < 4; ni++)
#pragma unroll
            for (int q = 0; q < 4; q++) { cg[mi][ni][q] = 0.f; cu[mi][ni][q] = 0.f; }

    const int NT = K >> 5;   // BK=32

#define UP_FETCH(KT) do {                                         \
        __half* s_ = smh + ((KT) % NSTAGE) * STG;                 \
        int off_ = (KT) << 5;                                     \
        cp16(s_ + sAo[0], apg[0] + off_);                         \
        cp16(s_ + sAo[1], apg[1] + off_);                         \
        cp16(s_ + 128 * SROW + sBo, b1g + off_);                  \
        cp16(s_ + 192 * SROW + sBo, b3g + off_);                  \
    } while (0)

    UP_FETCH(0); CP_COMMIT();
    UP_FETCH(1); CP_COMMIT();
    UP_FETCH(2); CP_COMMIT();

    for (int kt = 0; kt < NT; kt++) {
        if (kt + 3 < NT) UP_FETCH(kt + 3);
        CP_COMMIT();
        CP_WAIT3();
        __syncthreads();

        const __half* As  = smh + (kt % NSTAGE) * STG;
        const __half* B1s = As + 128 * SROW;
        const __half* B3s = As + 192 * SROW;

#pragma unroll
        for (int kk = 0; kk < 2; kk++) {
            const int kb = kk << 4;
            unsigned a[2][4];
            {
                const __half* p = As + (size_t)(wm + (lane & 15)) * SROW
                                   + kb + ((lane >> 4) << 3);
                ldsm4(a[0], p);
                ldsm4(a[1], p + 16 * SROW);
            }
            unsigned b1[4][2], b3[4][2];
            {
                int row = ((lane >> 4) << 3) + (lane & 7);
                int col = kb + (((lane >> 3) & 1) << 3);
                unsigned t0[4], t1[4];
                const __half* p = B1s + (size_t)(wn + row) * SROW + col;
                ldsm4(t0, p);
                ldsm4(t1, p + 16 * SROW);
                b1[0][0]=t0[0]; b1[0][1]=t0[1]; b1[1][0]=t0[2]; b1[1][1]=t0[3];
                b1[2][0]=t1[0]; b1[2][1]=t1[1]; b1[3][0]=t1[2]; b1[3][1]=t1[3];
                const __half* q = B3s + (size_t)(wn + row) * SROW + col;
                ldsm4(t0, q);
                ldsm4(t1, q + 16 * SROW);
                b3[0][0]=t0[0]; b3[0][1]=t0[1]; b3[1][0]=t0[2]; b3[1][1]=t0[3];
                b3[2][0]=t1[0]; b3[2][1]=t1[1]; b3[3][0]=t1[2]; b3[3][1]=t1[3];
            }
#pragma unroll
            for (int mi = 0; mi < 2; mi++)
#pragma unroll
                for (int ni = 0; ni < 4; ni++) {
                    mma_f16(cg[mi][ni], a[mi], b1[ni]);
                    mma_f16(cu[mi][ni], a[mi], b3[ni]);
                }
        }
        __syncthreads();
    }
#undef UP_FETCH

    const int lr = lane >> 2, lc2 = (lane & 3) << 1;
#pragma unroll
    for (int mi = 0; mi < 2; mi++)
#pragma unroll
        for (int ni = 0; ni < 4; ni++)
#pragma unroll
            for (int h = 0; h < 2; h++) {
                int row = (by << 7) + wm + mi * 16 + lr + h * 8;
                int col = (bx << 6) + wn + ni * 8 + lc2;
                float g0 = cg[mi][ni][h * 2], g1 = cg[mi][ni][h * 2 + 1];
                float u0 = cu[mi][ni][h * 2], u1 = cu[mi][ni][h * 2 + 1];
                __half2 hv = __floats2half2_rn(silu_f(g0) * u0, silu_f(g1) * u1);
                *reinterpret_cast<__half2*>(&Hout[(size_t)row * N + col]) = hv;
            }
}

// ---------------------------------------------------------------------------
// 5) down GEMM (fp16): Y = H W2^T. CTA 128x128, 256 thr, 8 warps (2m x 4n),
//    warp 64x32, ldmatrix + m16n8k16, 4-stage cp.async, 2 CTAs/SM.
// ---------------------------------------------------------------------------
__global__ void __launch_bounds__(256, 2) k_down(const __half* __restrict__ W2b,
                                                 int K, int routed,
                                                 float* __restrict__ Outp) {
    extern __shared__ __half smh[];
    const int bx = blockIdx.x, by = blockIdx.y;
    const int N = H_DIM;
    int e = 0;
    if (routed) { e = g_tile_e[by]; if (e < 0) return; }
    const __half* W2 = W2b + (size_t)e * N * K;
    const __half* Ain = routed ? g_Hbh : g_Hsh;

    const int tid = threadIdx.x;
    const int lane = tid & 31;
    const int warp = tid >> 5;
    const int wm = (warp >> 2) << 6;   // 0,64
    const int wn = (warp & 3) << 5;    // 0,32,64,96

    const __half *apg[2], *bpg[2]; int sLo[2];
#pragma unroll
    for (int i = 0; i < 2; i++) {
        int c = tid + 256 * i;
        int r = c >> 2, colh = (c & 3) << 3;
        apg[i] = Ain + (size_t)((by << 7) + r) * K + colh;
        bpg[i] = W2 + (size_t)((bx << 7) + r) * K + colh;
        sLo[i] = r * SROW + colh;
    }

    float cc[4][4][4];
#pragma unroll
    for (int mi = 0; mi < 4; mi++)
#pragma unroll
        for (int ni = 0; ni < 4; ni++)
#pragma unroll
            for (int q = 0; q < 4; q++) cc[mi][ni][q] = 0.f;

    const int NT = K >> 5;

#define DN_FETCH(KT) do {                                         \
        __half* s_ = smh + ((KT) % NSTAGE) * STG;                 \
        int off_ = (KT) << 5;                                     \
        cp16(s_ + sLo[0], apg[0] + off_);                         \
        cp16(s_ + sLo[1], apg[1] + off_);                         \
        cp16(s_ + 128 * SROW + sLo[0], bpg[0] + off_);            \
        cp16(s_ + 128 * SROW + sLo[1], bpg[1] + off_);            \
    } while (0)

    DN_FETCH(0); CP_COMMIT();
    DN_FETCH(1); CP_COMMIT();
    DN_FETCH(2); CP_COMMIT();

    for (int kt = 0; kt < NT; kt++) {
        if (kt + 3 < NT) DN_FETCH(kt + 3);
        CP_COMMIT();
        CP_WAIT3();
        __syncthreads();

        const __half* As = smh + (kt % NSTAGE) * STG;
        const __half* Bs = As + 128 * SROW;

#pragma unroll
        for (int kk = 0; kk < 2; kk++) {
            const int kb = kk << 4;
            unsigned a[4][4];
            {
                const __half* p = As + (size_t)(wm + (lane & 15)) * SROW
                                   + kb + ((lane >> 4) << 3);
#pragma unroll
                for (int mi = 0; mi < 4; mi++)
                    ldsm4(a[mi], p + mi * 16 * SROW);
            }
            unsigned b[4][2];
            {
                int row = ((lane >> 4) << 3) + (lane & 7);
                int col = kb + (((lane >> 3) & 1) << 3);
                unsigned t0[4], t1[4];
                const __half* p = Bs + (size_t)(wn + row) * SROW + col;
                ldsm4(t0, p);
                ldsm4(t1, p + 16 * SROW);
                b[0][0]=t0[0]; b[0][1]=t0[1]; b[1][0]=t0[2]; b[1][1]=t0[3];
                b[2][0]=t1[0]; b[2][1]=t1[1]; b[3][0]=t1[2]; b[3][1]=t1[3];
            }
#pragma unroll
            for (int mi = 0; mi < 4; mi++)
#pragma unroll
                for (int ni = 0; ni < 4; ni++)
                    mma_f16(cc[mi][ni], a[mi], b[ni]);
        }
        __syncthreads();
    }
#undef DN_FETCH

    const int lr = lane >> 2, lc2 = (lane & 3) << 1;
#pragma unroll
    for (int mi = 0; mi < 4; mi++)
#pragma unroll
        for (int h = 0; h < 2; h++) {
            int row = (by << 7) + wm + mi * 16 + lr + h * 8;
            if (routed) {
                int tok = g_rtok[row];
                if (tok < 0) continue;
                float w = g_rw[row];
                int slot = g_rslot[row];
                float* yrow = &g_Y[((size_t)tok * TOPK + slot) * H_DIM];
#pragma unroll
                for (int ni = 0; ni < 4; ni++) {
                    int col = (bx << 7) + wn + ni * 8 + lc2;
                    float2 v;
                    v.x = w * cc[mi][ni][h * 2];
                    v.y = w * cc[mi][ni][h * 2 + 1];
                    *reinterpret_cast<float2*>(&yrow[col]) = v;
                }
            } else {
                float* orow = &Outp[(size_t)row * H_DIM];
#pragma unroll
                for (int ni = 0; ni < 4; ni++) {
                    int col = (bx << 7) + wn + ni * 8 + lc2;
                    float2 v;
                    v.x = cc[mi][ni][h * 2];
                    v.y = cc[mi][ni][h * 2 + 1];
                    *reinterpret_cast<float2*>(&orow[col]) = v;
                }
            }
        }
}

// ---------------------------------------------------------------------------
// 6) combine: out += sum over 8 routed slots
// ---------------------------------------------------------------------------
__global__ void k_combine(float* __restrict__ out) {
    int i = blockIdx.x * blockDim.x + threadIdx.x;
    const float4* Y4 = reinterpret_cast<const float4*>(g_Y);
    float4* O4 = reinterpret_cast<float4*>(out);
    int t = i >> 9;
    int c = i & 511;
    float4 acc = O4[i];
    const float4* yb = Y4 + ((size_t)t * TOPK) * 512 + c;
#pragma unroll
    for (int s = 0; s < TOPK; s++) {
        float4 v = yb[(size_t)s * 512];
        acc.x += v.x; acc.y += v.y; acc.z += v.z; acc.w += v.w;
    }
    O4[i] = acc;
}

// ---------------------------------------------------------------------------
// Launch
// ---------------------------------------------------------------------------
extern "C" void kernel_launch(void* const* d_in, const int* in_sizes, int n_in,
                              void* d_out, int out_size) {
    const float* hs  = (const float*)d_in[0];
    const float* gw  = (const float*)d_in[1];
    const float* eb  = (const float*)d_in[2];
    const float* w1  = (const float*)d_in[3];
    const float* w3  = (const float*)d_in[4];
    const float* w2  = (const float*)d_in[5];
    const float* sw1 = (const float*)d_in[6];
    const float* sw3 = (const float*)d_in[7];
    const float* sw2 = (const float*)d_in[8];
    float* out = (float*)d_out;

    static __half* p_Xh   = nullptr;
    static __half* p_W1h  = nullptr;
    static __half* p_W3h  = nullptr;
    static __half* p_W2h  = nullptr;
    static __half* p_SW1h = nullptr;
    static __half* p_SW3h = nullptr;
    static __half* p_SW2h = nullptr;
    if (!p_Xh) {
        cudaGetSymbolAddress((void**)&p_Xh,   g_Xh);
        cudaGetSymbolAddress((void**)&p_W1h,  g_W1h);
        cudaGetSymbolAddress((void**)&p_W3h,  g_W3h);
        cudaGetSymbolAddress((void**)&p_W2h,  g_W2h);
        cudaGetSymbolAddress((void**)&p_SW1h, g_SW1h);
        cudaGetSymbolAddress((void**)&p_SW3h, g_SW3h);
        cudaGetSymbolAddress((void**)&p_SW2h, g_SW2h);
        cudaFuncSetAttribute((const void*)k_up,
                             cudaFuncAttributeMaxDynamicSharedMemorySize,
                             NSTAGE * STG * (int)sizeof(__half));
        cudaFuncSetAttribute((const void*)k_down,
                             cudaFuncAttributeMaxDynamicSharedMemorySize,
                             NSTAGE * STG * (int)sizeof(__half));
    }

    // fp32 -> fp16 pre-conversion of all GEMM operands
    {
        int n8;
        n8 = T_TOK * H_DIM / 8;
        k_cvth<<<(n8 + 255) / 256, 256>>>((const float4*)hs, (uint4*)p_Xh, n8);
        n8 = E_NUM * I_DIM * H_DIM / 8;
        k_cvth<<<(n8 + 255) / 256, 256>>>((const float4*)w1, (uint4*)p_W1h, n8);
        k_cvth<<<(n8 + 255) / 256, 256>>>((const float4*)w3, (uint4*)p_W3h, n8);
        k_cvth<<<(n8 + 255) / 256, 256>>>((const float4*)w2, (uint4*)p_W2h, n8);
        n8 = IS_DIM * H_DIM / 8;
        k_cvth<<<(n8 + 255) / 256, 256>>>((const float4*)sw1, (uint4*)p_SW1h, n8);
        k_cvth<<<(n8 + 255) / 256, 256>>>((const float4*)sw3, (uint4*)p_SW3h, n8);
        k_cvth<<<(n8 + 255) / 256, 256>>>((const float4*)sw2, (uint4*)p_SW2h, n8);
    }

    k_clear<<<512, 256>>>();
    k_router<<<T_TOK / 4, 128>>>(hs, gw, eb);
    k_offsets<<<1, 1024>>>();
    k_scatter<<<E_NUM, 1024>>>();

    const int smem = NSTAGE * STG * (int)sizeof(__half);

    // routed experts
    k_up<<<dim3(I_DIM / 64, NT_MAX), 256, smem>>>(p_W1h, p_W3h, H_DIM, I_DIM, 1);
    k_down<<<dim3(H_DIM / 128, NT_MAX), 256, smem>>>(p_W2h, I_DIM, 1, nullptr);

    // shared expert (writes d_out directly)
    k_up<<<dim3(IS_DIM / 64, T_TOK / 128), 256, smem>>>(p_SW1h, p_SW3h, H_DIM, IS_DIM, 0);
    k_down<<<dim3(H_DIM / 128, T_TOK / 128), 256, smem>>>(p_SW2h, IS_DIM, 0, out);

    // final combine
    k_combine<<<(T_TOK * H_DIM / 4) / 256, 256>>>(out);

    (void)in_sizes; (void)n_in; (void)out_size;
}

// round 15
// speedup vs baseline: 1.9212x; 1.0635x over previous
#include <cuda_runtime.h>
#include <cuda_fp16.h>
#include <cstdint>
#include <math.h>

// ---------------------------------------------------------------------------
// Problem constants
// ---------------------------------------------------------------------------
#define T_TOK   4096
#define H_DIM   2048
#define E_NUM   32
#define I_DIM   1024
#define IS_DIM  2048
#define TOPK    8
#define NGRP    8
#define TOPKG   4

#define NT_MAX   288             // 32768/128 + 32 experts of pad tiles
#define ROWS_MAX (NT_MAX * 128)  // 36864

// GEMM tile config (fp16 mma.sync path)
#define BK     32                // K per tile (halves)
#define SROW   40                // smem row stride in halves (80B; ldmatrix conflict-free)
#define STG    (256 * SROW)      // halves per pipeline stage (A:128 rows + B:128 rows)
#define NSTAGE 4

// ---------------------------------------------------------------------------
// Device scratch
// ---------------------------------------------------------------------------
__device__ float         g_Wdense[T_TOK * E_NUM];
__device__ unsigned char g_Slot[T_TOK * E_NUM];
__device__ int           g_counts[E_NUM];
__device__ int           g_tile_e[NT_MAX];
__device__ int           g_rtok[ROWS_MAX];
__device__ float         g_rw[ROWS_MAX];
__device__ unsigned char g_rslot[ROWS_MAX];

// fp16-preconverted operands
__device__ __half g_Xh[(size_t)T_TOK * H_DIM];
__device__ __half g_W1h[(size_t)E_NUM * I_DIM * H_DIM];
__device__ __half g_W3h[(size_t)E_NUM * I_DIM * H_DIM];
__device__ __half g_W2h[(size_t)E_NUM * H_DIM * I_DIM];
__device__ __half g_SW1h[(size_t)IS_DIM * H_DIM];
__device__ __half g_SW3h[(size_t)IS_DIM * H_DIM];
__device__ __half g_SW2h[(size_t)H_DIM * IS_DIM];

__device__ __half g_Hbh[(size_t)ROWS_MAX * I_DIM];   // routed intermediate
__device__ __half g_Hsh[(size_t)T_TOK * IS_DIM];     // shared intermediate
__device__ float  g_Y[(size_t)T_TOK * TOPK * H_DIM]; // per-slot routed outputs

// ---------------------------------------------------------------------------
// Helpers
// ---------------------------------------------------------------------------
__device__ __forceinline__ void mma_f16(float* c, const unsigned* a, const unsigned* b) {
    asm volatile(
        "mma.sync.aligned.m16n8k16.row.col.f32.f16.f16.f32 "
        "{%0,%1,%2,%3}, {%4,%5,%6,%7}, {%8,%9}, {%0,%1,%2,%3};\n"
        : "+f"(c[0]), "+f"(c[1]), "+f"(c[2]), "+f"(c[3])
        : "r"(a[0]), "r"(a[1]), "r"(a[2]), "r"(a[3]), "r"(b[0]), "r"(b[1]));
}

__device__ __forceinline__ void ldsm4(unsigned* r, const void* p) {
    unsigned a = (unsigned)__cvta_generic_to_shared(p);
    asm volatile("ldmatrix.sync.aligned.m8n8.x4.shared.b16 {%0,%1,%2,%3}, [%4];\n"
                 : "=r"(r[0]), "=r"(r[1]), "=r"(r[2]), "=r"(r[3]) : "r"(a));
}

__device__ __forceinline__ void cp16(void* sptr, const void* gptr) {
    unsigned sa = (unsigned)__cvta_generic_to_shared(sptr);
    asm volatile("cp.async.cg.shared.global [%0], [%1], 16;\n" :: "r"(sa), "l"(gptr));
}
#define CP_COMMIT() asm volatile("cp.async.commit_group;\n")
#define CP_WAIT2()  asm volatile("cp.async.wait_group 2;\n")

__device__ __forceinline__ float silu_f(float x) { return x / (1.f + __expf(-x)); }

// ---------------------------------------------------------------------------
// merged fp32->fp16 conversion for ALL operands (one launch) + counts clear
// segment layout in 8-element units
// ---------------------------------------------------------------------------
#define N8_X   (T_TOK * H_DIM / 8)                 // 1,048,576
#define N8_W   (E_NUM * I_DIM * H_DIM / 8)         // 8,388,608
#define N8_SW  (IS_DIM * H_DIM / 8)                //   524,288
#define N8_TOT (N8_X + 3 * N8_W + 3 * N8_SW)       // 27,787,264

__device__ __forceinline__ void cv8(const float4* in, uint4* out, int i) {
    float4 v0 = in[2 * i];
    float4 v1 = in[2 * i + 1];
    __half2 h[4];
    h[0] = __floats2half2_rn(v0.x, v0.y);
    h[1] = __floats2half2_rn(v0.z, v0.w);
    h[2] = __floats2half2_rn(v1.x, v1.y);
    h[3] = __floats2half2_rn(v1.z, v1.w);
    out[i] = *reinterpret_cast<uint4*>(h);
}

__global__ void k_cvtall(const float4* __restrict__ x,
                         const float4* __restrict__ w1, const float4* __restrict__ w3,
                         const float4* __restrict__ w2, const float4* __restrict__ sw1,
                         const float4* __restrict__ sw3, const float4* __restrict__ sw2) {
    int i = blockIdx.x * blockDim.x + threadIdx.x;
    if (i < E_NUM) g_counts[i] = 0;
    if (i >= N8_TOT) return;
    if (i < N8_X) { cv8(x, (uint4*)g_Xh, i); return; }
    i -= N8_X;
    if (i < N8_W) { cv8(w1, (uint4*)g_W1h, i); return; }
    i -= N8_W;
    if (i < N8_W) { cv8(w3, (uint4*)g_W3h, i); return; }
    i -= N8_W;
    if (i < N8_W) { cv8(w2, (uint4*)g_W2h, i); return; }
    i -= N8_W;
    if (i < N8_SW) { cv8(sw1, (uint4*)g_SW1h, i); return; }
    i -= N8_SW;
    if (i < N8_SW) { cv8(sw3, (uint4*)g_SW3h, i); return; }
    i -= N8_SW;
    cv8(sw2, (uint4*)g_SW2h, i);
}

// ---------------------------------------------------------------------------
// 1) router (one warp per token) — writes full dense rows (no k_clear needed)
// ---------------------------------------------------------------------------
__global__ void __launch_bounds__(128) k_router(const float* __restrict__ X,
                                                const float* __restrict__ GW,
                                                const float* __restrict__ EB) {
    const int warp = threadIdx.x >> 5;
    const int lane = threadIdx.x & 31;
    const int t = blockIdx.x * 4 + warp;

    __shared__ float ssw[4][32];
    __shared__ float ssc[4][32];
    __shared__ float sout[4][32];
    __shared__ unsigned char sslot[4][32];

    const float* x = X + (size_t)t * H_DIM;
    const float* g = GW + (size_t)lane * H_DIM;
    float a0=0.f,a1=0.f,a2=0.f,a3=0.f,a4=0.f,a5=0.f,a6=0.f,a7=0.f;
    for (int k = 0; k < H_DIM; k += 8) {
        float4 xv0 = *(const float4*)(x + k);
        float4 gv0 = *(const float4*)(g + k);
        float4 xv1 = *(const float4*)(x + k + 4);
        float4 gv1 = *(const float4*)(g + k + 4);
        a0 += xv0.x * gv0.x;  a1 += xv0.y * gv0.y;
        a2 += xv0.z * gv0.z;  a3 += xv0.w * gv0.w;
        a4 += xv1.x * gv1.x;  a5 += xv1.y * gv1.y;
        a6 += xv1.z * gv1.z;  a7 += xv1.w * gv1.w;
    }
    float logit = ((a0 + a4) + (a1 + a5)) + ((a2 + a6) + (a3 + a7));

    double scd = 1.0 / (1.0 + exp(-(double)logit));
    float sc = (float)scd;
    float sw = sc + EB[lane];
    ssw[warp][lane] = sw;
    ssc[warp][lane] = sc;
    sout[warp][lane] = 0.f;
    sslot[warp][lane] = 0;
    __syncwarp();

    if (lane == 0) {
        const float* swp = ssw[warp];
        const float* scp = ssc[warp];
        float gsc[NGRP];
#pragma unroll
        for (int gg = 0; gg < NGRP; gg++) {
            float m1 = -1e30f, m2 = -1e30f;
#pragma unroll
            for (int j = 0; j < 4; j++) {
                float v = swp[gg * 4 + j];
                if (v > m1) { m2 = m1; m1 = v; }
                else if (v > m2) m2 = v;
            }
            gsc[gg] = m1 + m2;
        }
        unsigned gmask = 0;
        for (int it = 0; it < TOPKG; it++) {
            int bg = 0; float bv = -1e30f;
            for (int gg = 0; gg < NGRP; gg++)
                if (!((gmask >> gg) & 1) && gsc[gg] > bv) { bv = gsc[gg]; bg = gg; }
            gmask |= 1u << bg;
        }
        int idx[TOPK]; float wsel[TOPK]; float wsum = 0.f;
        unsigned taken = 0;
        for (int it = 0; it < TOPK; it++) {
            int be = 0; float bv = -1e30f;
            for (int ee = 0; ee < E_NUM; ee++) {
                if (!((gmask >> (ee >> 2)) & 1)) continue;
                if ((taken >> ee) & 1) continue;
                if (swp[ee] > bv) { bv = swp[ee]; be = ee; }
            }
            taken |= 1u << be;
            idx[it] = be;
            wsel[it] = scp[be];
            wsum += scp[be];
        }
        float inv = 2.5f / (wsum + 1e-20f);
        for (int it = 0; it < TOPK; it++) {
            int ee = idx[it];
            sout[warp][ee] = wsel[it] * inv;
            sslot[warp][ee] = (unsigned char)it;
            atomicAdd(&g_counts[ee], 1);
        }
    }
    __syncwarp();
    g_Wdense[(size_t)t * E_NUM + lane] = sout[warp][lane];
    g_Slot[(size_t)t * E_NUM + lane]   = sslot[warp][lane];
}

// ---------------------------------------------------------------------------
// 2) scatter (folds offsets/tile-map/pad-init): one block per expert
// ---------------------------------------------------------------------------
__global__ void __launch_bounds__(1024) k_scatter() {
    const int e = blockIdx.x;
    const int tid = threadIdx.x;

    __shared__ int soff[E_NUM], spad[E_NUM];
    if (tid < 32) {
        int c = g_counts[tid];
        int p = (c + 127) & ~127;
        int incl = p;
#pragma unroll
        for (int d = 1; d < 32; d <<= 1) {
            int v = __shfl_up_sync(0xFFFFFFFFu, incl, d);
            if (tid >= d) incl += v;
        }
        soff[tid] = incl - p;
        spad[tid] = p;
    }
    __syncthreads();

    // block 0 writes the 128-row tile map
    if (e == 0) {
        for (int tt = tid; tt < NT_MAX; tt += blockDim.x) {
            int owner = -1;
            int r = tt << 7;
#pragma unroll
            for (int ee = 0; ee < E_NUM; ee++)
                if (r >= soff[ee] && r < soff[ee] + spad[ee]) owner = ee;
            g_tile_e[tt] = owner;
        }
    }
    // pad-row init for this expert's region
    {
        int base = soff[e] + g_counts[e];
        int end  = soff[e] + spad[e];
        for (int i = base + tid; i < end; i += blockDim.x) {
            g_rtok[i] = -1;
            g_rw[i] = 0.f;
            g_rslot[i] = 0;
        }
    }

    const int base_t = tid * 4;
    float w[4]; int cnt = 0;
#pragma unroll
    for (int i = 0; i < 4; i++) {
        w[i] = g_Wdense[(size_t)(base_t + i) * E_NUM + e];
        cnt += (w[i] != 0.f);
    }
    const int lane = tid & 31, wid = tid >> 5;
    int incl = cnt;
#pragma unroll
    for (int d = 1; d < 32; d <<= 1) {
        int v = __shfl_up_sync(0xFFFFFFFFu, incl, d);
        if (lane >= d) incl += v;
    }
    __shared__ int wsum[32];
    if (lane == 31) wsum[wid] = incl;
    __syncthreads();
    if (wid == 0) {
        int v = wsum[lane];
#pragma unroll
        for (int d = 1; d < 32; d <<= 1) {
            int u = __shfl_up_sync(0xFFFFFFFFu, v, d);
            if (lane >= d) v += u;
        }
        wsum[lane] = v;
    }
    __syncthreads();
    int excl = incl - cnt + (wid ? wsum[wid - 1] : 0);
    int pos = soff[e] + excl;
#pragma unroll
    for (int i = 0; i < 4; i++) {
        if (w[i] != 0.f) {
            g_rtok[pos] = base_t + i;
            g_rw[pos] = w[i];
            g_rslot[pos] = g_Slot[(size_t)(base_t + i) * E_NUM + e];
            pos++;
        }
    }
}

// ---------------------------------------------------------------------------
// 4) up GEMM (fp16): H = silu(A W1^T) * (A W3^T). CTA 128x64 dual, 256 thr,
//    8 warps (4m x 2n), warp 32x32, m16n8k16, 4-stage cp.async, 2 CTAs/SM.
//    Single barrier per ktile; all ldmatrix hoisted ahead of all MMAs.
// ---------------------------------------------------------------------------
__global__ void __launch_bounds__(256, 2) k_up(const __half* __restrict__ W1b,
                                               const __half* __restrict__ W3b,
                                               int K, int N, int routed) {
    extern __shared__ __half smh[];
    const int bx = blockIdx.x, by = blockIdx.y;
    int e = 0;
    if (routed) { e = g_tile_e[by]; if (e < 0) return; }
    const size_t wstride = (size_t)N * K;
    const __half* W1 = W1b + (size_t)e * wstride;
    const __half* W3 = W3b + (size_t)e * wstride;
    __half* Hout = routed ? g_Hbh : g_Hsh;

    const int tid = threadIdx.x;
    const int lane = tid & 31;
    const int warp = tid >> 5;
    const int wm = (warp >> 1) << 5;   // 0,32,64,96
    const int wn = (warp & 1) << 5;    // 0,32

    const __half* apg[2]; int sAo[2];
#pragma unroll
    for (int i = 0; i < 2; i++) {
        int c = tid + 256 * i;
        int r = c >> 2, colh = (c & 3) << 3;
        int grow = (by << 7) + r;
        int tok = routed ? g_rtok[grow] : grow;
        if (tok < 0) tok = 0;
        apg[i] = g_Xh + (size_t)tok * K + colh;
        sAo[i] = r * SROW + colh;
    }
    const __half *b1g, *b3g; int sBo;
    {
        int r = tid >> 2, colh = (tid & 3) << 3;
        b1g = W1 + (size_t)((bx << 6) + r) * K + colh;
        b3g = W3 + (size_t)((bx << 6) + r) * K + colh;
        sBo = r * SROW + colh;
    }

    float cg[2][4][4], cu[2][4][4];
#pragma unroll
    for (int mi = 0; mi < 2; mi++)
#pragma unroll
        for (int ni = 0; ni < 4; ni++)
#pragma unroll
            for (int q = 0; q < 4; q++) { cg[mi][ni][q] = 0.f; cu[mi][ni][q] = 0.f; }

    const int NT = K >> 5;   // BK=32

#define UP_FETCH(KT) do {                                         \
        __half* s_ = smh + ((KT) % NSTAGE) * STG;                 \
        int off_ = (KT) << 5;                                     \
        cp16(s_ + sAo[0], apg[0] + off_);                         \
        cp16(s_ + sAo[1], apg[1] + off_);                         \
        cp16(s_ + 128 * SROW + sBo, b1g + off_);                  \
        cp16(s_ + 192 * SROW + sBo, b3g + off_);                  \
    } while (0)

    UP_FETCH(0); CP_COMMIT();
    UP_FETCH(1); CP_COMMIT();
    UP_FETCH(2); CP_COMMIT();

    for (int kt = 0; kt < NT; kt++) {
        CP_WAIT2();
        __syncthreads();
        if (kt + 3 < NT) UP_FETCH(kt + 3);
        CP_COMMIT();

        const __half* As  = smh + (kt % NSTAGE) * STG;
        const __half* B1s = As + 128 * SROW;
        const __half* B3s = As + 192 * SROW;

        // hoist all fragment loads for both kk halves
        unsigned a[2][2][4], b1[2][4][2], b3[2][4][2];
#pragma unroll
        for (int kk = 0; kk < 2; kk++) {
            const int kb = kk << 4;
            {
                const __half* p = As + (size_t)(wm + (lane & 15)) * SROW
                                   + kb + ((lane >> 4) << 3);
                ldsm4(a[kk][0], p);
                ldsm4(a[kk][1], p + 16 * SROW);
            }
            {
                int row = ((lane >> 4) << 3) + (lane & 7);
                int col = kb + (((lane >> 3) & 1) << 3);
                unsigned t0[4], t1[4];
                const __half* p = B1s + (size_t)(wn + row) * SROW + col;
                ldsm4(t0, p);
                ldsm4(t1, p + 16 * SROW);
                b1[kk][0][0]=t0[0]; b1[kk][0][1]=t0[1]; b1[kk][1][0]=t0[2]; b1[kk][1][1]=t0[3];
                b1[kk][2][0]=t1[0]; b1[kk][2][1]=t1[1]; b1[kk][3][0]=t1[2]; b1[kk][3][1]=t1[3];
                const __half* q = B3s + (size_t)(wn + row) * SROW + col;
                ldsm4(t0, q);
                ldsm4(t1, q + 16 * SROW);
                b3[kk][0][0]=t0[0]; b3[kk][0][1]=t0[1]; b3[kk][1][0]=t0[2]; b3[kk][1][1]=t0[3];
                b3[kk][2][0]=t1[0]; b3[kk][2][1]=t1[1]; b3[kk][3][0]=t1[2]; b3[kk][3][1]=t1[3];
            }
        }
#pragma unroll
        for (int kk = 0; kk < 2; kk++)
#pragma unroll
            for (int mi = 0; mi < 2; mi++)
#pragma unroll
                for (int ni = 0; ni < 4; ni++) {
                    mma_f16(cg[mi][ni], a[kk][mi], b1[kk][ni]);
                    mma_f16(cu[mi][ni], a[kk][mi], b3[kk][ni]);
                }
    }
#undef UP_FETCH

    const int lr = lane >> 2, lc2 = (lane & 3) << 1;
#pragma unroll
    for (int mi = 0; mi < 2; mi++)
#pragma unroll
        for (int ni = 0; ni < 4; ni++)
#pragma unroll
            for (int h = 0; h < 2; h++) {
                int row = (by << 7) + wm + mi * 16 + lr + h * 8;
                int col = (bx << 6) + wn + ni * 8 + lc2;
                float g0 = cg[mi][ni][h * 2], g1 = cg[mi][ni][h * 2 + 1];
                float u0 = cu[mi][ni][h * 2], u1 = cu[mi][ni][h * 2 + 1];
                __half2 hv = __floats2half2_rn(silu_f(g0) * u0, silu_f(g1) * u1);
                *reinterpret_cast<__half2*>(&Hout[(size_t)row * N + col]) = hv;
            }
}

// ---------------------------------------------------------------------------
// 5) down GEMM (fp16): Y = H W2^T. CTA 128x128, 256 thr, 8 warps (2m x 4n),
//    warp 64x32, same single-barrier + hoisted-fragment structure.
// ---------------------------------------------------------------------------
__global__ void __launch_bounds__(256, 2) k_down(const __half* __restrict__ W2b,
                                                 int K, int routed,
                                                 float* __restrict__ Outp) {
    extern __shared__ __half smh[];
    const int bx = blockIdx.x, by = blockIdx.y;
    const int N = H_DIM;
    int e = 0;
    if (routed) { e = g_tile_e[by]; if (e < 0) return; }
    const __half* W2 = W2b + (size_t)e * N * K;
    const __half* Ain = routed ? g_Hbh : g_Hsh;

    const int tid = threadIdx.x;
    const int lane = tid & 31;
    const int warp = tid >> 5;
    const int wm = (warp >> 2) << 6;   // 0,64
    const int wn = (warp & 3) << 5;    // 0,32,64,96

    const __half *apg[2], *bpg[2]; int sLo[2];
#pragma unroll
    for (int i = 0; i < 2; i++) {
        int c = tid + 256 * i;
        int r = c >> 2, colh = (c & 3) << 3;
        apg[i] = Ain + (size_t)((by << 7) + r) * K + colh;
        bpg[i] = W2 + (size_t)((bx << 7) + r) * K + colh;
        sLo[i] = r * SROW + colh;
    }

    float cc[4][4][4];
#pragma unroll
    for (int mi = 0; mi < 4; mi++)
#pragma unroll
        for (int ni = 0; ni < 4; ni++)
#pragma unroll
            for (int q = 0; q < 4; q++) cc[mi][ni][q] = 0.f;

    const int NT = K >> 5;

#define DN_FETCH(KT) do {                                         \
        __half* s_ = smh + ((KT) % NSTAGE) * STG;                 \
        int off_ = (KT) << 5;                                     \
        cp16(s_ + sLo[0], apg[0] + off_);                         \
        cp16(s_ + sLo[1], apg[1] + off_);                         \
        cp16(s_ + 128 * SROW + sLo[0], bpg[0] + off_);            \
        cp16(s_ + 128 * SROW + sLo[1], bpg[1] + off_);            \
    } while (0)

    DN_FETCH(0); CP_COMMIT();
    DN_FETCH(1); CP_COMMIT();
    DN_FETCH(2); CP_COMMIT();

    for (int kt = 0; kt < NT; kt++) {
        CP_WAIT2();
        __syncthreads();
        if (kt + 3 < NT) DN_FETCH(kt + 3);
        CP_COMMIT();

        const __half* As = smh + (kt % NSTAGE) * STG;
        const __half* Bs = As + 128 * SROW;

        unsigned a[2][4][4], b[2][4][2];
#pragma unroll
        for (int kk = 0; kk < 2; kk++) {
            const int kb = kk << 4;
            {
                const __half* p = As + (size_t)(wm + (lane & 15)) * SROW
                                   + kb + ((lane >> 4) << 3);
#pragma unroll
                for (int mi = 0; mi < 4; mi++)
                    ldsm4(a[kk][mi], p + mi * 16 * SROW);
            }
            {
                int row = ((lane >> 4) << 3) + (lane & 7);
                int col = kb + (((lane >> 3) & 1) << 3);
                unsigned t0[4], t1[4];
                const __half* p = Bs + (size_t)(wn + row) * SROW + col;
                ldsm4(t0, p);
                ldsm4(t1, p + 16 * SROW);
                b[kk][0][0]=t0[0]; b[kk][0][1]=t0[1]; b[kk][1][0]=t0[2]; b[kk][1][1]=t0[3];
                b[kk][2][0]=t1[0]; b[kk][2][1]=t1[1]; b[kk][3][0]=t1[2]; b[kk][3][1]=t1[3];
            }
        }
#pragma unroll
        for (int kk = 0; kk < 2; kk++)
#pragma unroll
            for (int mi = 0; mi < 4; mi++)
#pragma unroll
                for (int ni = 0; ni < 4; ni++)
                    mma_f16(cc[mi][ni], a[kk][mi], b[kk][ni]);
    }
#undef DN_FETCH

    const int lr = lane >> 2, lc2 = (lane & 3) << 1;
#pragma unroll
    for (int mi = 0; mi < 4; mi++)
#pragma unroll
        for (int h = 0; h < 2; h++) {
            int row = (by << 7) + wm + mi * 16 + lr + h * 8;
            if (routed) {
                int tok = g_rtok[row];
                if (tok < 0) continue;
                float w = g_rw[row];
                int slot = g_rslot[row];
                float* yrow = &g_Y[((size_t)tok * TOPK + slot) * H_DIM];
#pragma unroll
                for (int ni = 0; ni < 4; ni++) {
                    int col = (bx << 7) + wn + ni * 8 + lc2;
                    float2 v;
                    v.x = w * cc[mi][ni][h * 2];
                    v.y = w * cc[mi][ni][h * 2 + 1];
                    *reinterpret_cast<float2*>(&yrow[col]) = v;
                }
            } else {
                float* orow = &Outp[(size_t)row * H_DIM];
#pragma unroll
                for (int ni = 0; ni < 4; ni++) {
                    int col = (bx << 7) + wn + ni * 8 + lc2;
                    float2 v;
                    v.x = cc[mi][ni][h * 2];
                    v.y = cc[mi][ni][h * 2 + 1];
                    *reinterpret_cast<float2*>(&orow[col]) = v;
                }
            }
        }
}

// ---------------------------------------------------------------------------
// 6) combine: out += sum over 8 routed slots
// ---------------------------------------------------------------------------
__global__ void k_combine(float* __restrict__ out) {
    int i = blockIdx.x * blockDim.x + threadIdx.x;
    const float4* Y4 = reinterpret_cast<const float4*>(g_Y);
    float4* O4 = reinterpret_cast<float4*>(out);
    int t = i >> 9;
    int c = i & 511;
    float4 acc = O4[i];
    const float4* yb = Y4 + ((size_t)t * TOPK) * 512 + c;
#pragma unroll
    for (int s = 0; s < TOPK; s++) {
        float4 v = yb[(size_t)s * 512];
        acc.x += v.x; acc.y += v.y; acc.z += v.z; acc.w += v.w;
    }
    O4[i] = acc;
}

// ---------------------------------------------------------------------------
// Launch
// ---------------------------------------------------------------------------
extern "C" void kernel_launch(void* const* d_in, const int* in_sizes, int n_in,
                              void* d_out, int out_size) {
    const float* hs  = (const float*)d_in[0];
    const float* gw  = (const float*)d_in[1];
    const float* eb  = (const float*)d_in[2];
    const float* w1  = (const float*)d_in[3];
    const float* w3  = (const float*)d_in[4];
    const float* w2  = (const float*)d_in[5];
    const float* sw1 = (const float*)d_in[6];
    const float* sw3 = (const float*)d_in[7];
    const float* sw2 = (const float*)d_in[8];
    float* out = (float*)d_out;

    static __half* p_W1h = nullptr;   // sentinel for one-time setup
    if (!p_W1h) {
        cudaGetSymbolAddress((void**)&p_W1h, g_W1h);
        cudaFuncSetAttribute((const void*)k_up,
                             cudaFuncAttributeMaxDynamicSharedMemorySize,
                             NSTAGE * STG * (int)sizeof(__half));
        cudaFuncSetAttribute((const void*)k_down,
                             cudaFuncAttributeMaxDynamicSharedMemorySize,
                             NSTAGE * STG * (int)sizeof(__half));
    }
    static __half *p_W3h = nullptr, *p_W2h = nullptr, *p_SW1h = nullptr,
                  *p_SW3h = nullptr, *p_SW2h = nullptr;
    if (!p_W3h) {
        cudaGetSymbolAddress((void**)&p_W3h,  g_W3h);
        cudaGetSymbolAddress((void**)&p_W2h,  g_W2h);
        cudaGetSymbolAddress((void**)&p_SW1h, g_SW1h);
        cudaGetSymbolAddress((void**)&p_SW3h, g_SW3h);
        cudaGetSymbolAddress((void**)&p_SW2h, g_SW2h);
    }

    // 0) merged fp32->fp16 conversion (also zeroes g_counts)
    k_cvtall<<<(N8_TOT + 255) / 256, 256>>>(
        (const float4*)hs, (const float4*)w1, (const float4*)w3, (const float4*)w2,
        (const float4*)sw1, (const float4*)sw3, (const float4*)sw2);

    // 1) routing
    k_router<<<T_TOK / 4, 128>>>(hs, gw, eb);
    k_scatter<<<E_NUM, 1024>>>();

    const int smem = NSTAGE * STG * (int)sizeof(__half);

    // routed experts
    k_up<<<dim3(I_DIM / 64, NT_MAX), 256, smem>>>(p_W1h, p_W3h, H_DIM, I_DIM, 1);
    k_down<<<dim3(H_DIM / 128, NT_MAX), 256, smem>>>(p_W2h, I_DIM, 1, nullptr);

    // shared expert (writes d_out directly)
    k_up<<<dim3(IS_DIM / 64, T_TOK / 128), 256, smem>>>(p_SW1h, p_SW3h, H_DIM, IS_DIM, 0);
    k_down<<<dim3(H_DIM / 128, T_TOK / 128), 256, smem>>>(p_SW2h, IS_DIM, 0, out);

    // final combine
    k_combine<<<(T_TOK * H_DIM / 4) / 256, 256>>>(out);

    (void)in_sizes; (void)n_in; (void)out_size;
}